// round 1
// baseline (speedup 1.0000x reference)
#include <cuda_runtime.h>
#include <math.h>

// Problem dims (fixed)
#define BB 2
#define SS_ 2048
#define DD 2048
#define HH 16
#define DH_ 128
#define FF_ 8192
#define ROWS 4096            // B*S

// ---------------- scratch (device globals; no allocation) ----------------
__device__ float g_h   [(size_t)ROWS * DD];   // ln1 out, later h2
__device__ float g_q   [(size_t)ROWS * DD];
__device__ float g_k   [(size_t)ROWS * DD];
__device__ float g_v   [(size_t)ROWS * DD];
__device__ float g_ctx [(size_t)ROWS * DD];
__device__ float g_res [(size_t)ROWS * DD];
__device__ float g_ffn [(size_t)ROWS * FF_];

// ---------------- LayerNorm: one block per row ----------------
__global__ void ln_kernel(const float* __restrict__ x,
                          const float* __restrict__ g,
                          const float* __restrict__ b,
                          float* __restrict__ out) {
    __shared__ float red[256];
    const int row = blockIdx.x;
    const int tid = threadIdx.x;
    const float* xr = x + (long long)row * DD;

    float s = 0.f;
    for (int i = tid; i < DD; i += 256) s += xr[i];
    red[tid] = s; __syncthreads();
    for (int o = 128; o > 0; o >>= 1) { if (tid < o) red[tid] += red[tid + o]; __syncthreads(); }
    const float mean = red[0] * (1.f / DD);
    __syncthreads();

    float v = 0.f;
    for (int i = tid; i < DD; i += 256) { float d = xr[i] - mean; v += d * d; }
    red[tid] = v; __syncthreads();
    for (int o = 128; o > 0; o >>= 1) { if (tid < o) red[tid] += red[tid + o]; __syncthreads(); }
    const float rstd = rsqrtf(red[0] * (1.f / DD) + 1e-5f);

    float* orow = out + (long long)row * DD;
    for (int i = tid; i < DD; i += 256)
        orow[i] = (xr[i] - mean) * rstd * g[i] + b[i];
}

// ---------------- RoPE (GPT-J interleaved), applies to q and k ----------------
__global__ void rope_kernel(float* __restrict__ q, float* __restrict__ k,
                            const int* __restrict__ pos) {
    // one thread per (b,s,h,pair) ; pairs = DH/2 = 64
    long long idx = (long long)blockIdx.x * blockDim.x + threadIdx.x;
    const long long total = (long long)ROWS * HH * 64;
    if (idx >= total) return;
    const int i = (int)(idx & 63);          // pair index 0..63
    long long t = idx >> 6;
    const int h = (int)(t % HH); t /= HH;
    const int s = (int)(t % SS_);
    const int b = (int)(t / SS_);

    const int p = pos[b * SS_ + s];
    const float inv = exp10f(-(float)i * (1.f / 16.f));  // 10000^(-2i/128)
    const float ang = (float)p * inv;
    float sn, cs;
    __sincosf(ang, &sn, &cs);
    // use accurate versions to be safe
    sn = sinf(ang); cs = cosf(ang);

    const long long base = ((((long long)b * SS_ + s) * HH + h) * DH_) + 2 * i;
    {
        float x0 = q[base], x1 = q[base + 1];
        q[base]     = x0 * cs - x1 * sn;
        q[base + 1] = x1 * cs + x0 * sn;
    }
    {
        float x0 = k[base], x1 = k[base + 1];
        k[base]     = x0 * cs - x1 * sn;
        k[base + 1] = x1 * cs + x0 * sn;
    }
}

// ---------------- fused scores + causal softmax (one block per (b,h,q-row)) ----------
__global__ void attn_kernel(const float* __restrict__ q,
                            const float* __restrict__ k,
                            float* __restrict__ w) {
    __shared__ float qs[DH_];
    __shared__ float sc[SS_];
    __shared__ float red[256];

    const int qi = blockIdx.x, h = blockIdx.y, b = blockIdx.z;
    const int tid = threadIdx.x;

    const float* qrow = q + (((long long)b * SS_ + qi) * HH + h) * DH_;
    for (int i = tid; i < DH_; i += 256) qs[i] = qrow[i];
    __syncthreads();

    const int n = qi + 1;
    const float4* q4 = (const float4*)qs;

    float lmax = -1e30f;
    for (int j = tid; j < n; j += 256) {
        const float4* k4 = (const float4*)(k + (((long long)b * SS_ + j) * HH + h) * DH_);
        float d = 0.f;
#pragma unroll
        for (int c = 0; c < DH_ / 4; c++) {
            float4 kv = k4[c]; float4 qv = q4[c];
            d += kv.x * qv.x + kv.y * qv.y + kv.z * qv.z + kv.w * qv.w;
        }
        sc[j] = d;
        lmax = fmaxf(lmax, d);
    }
    red[tid] = lmax; __syncthreads();
    for (int o = 128; o > 0; o >>= 1) { if (tid < o) red[tid] = fmaxf(red[tid], red[tid + o]); __syncthreads(); }
    const float gmax = red[0];
    __syncthreads();

    float lsum = 0.f;
    for (int j = tid; j < n; j += 256) {
        float e = expf(sc[j] - gmax);
        sc[j] = e;
        lsum += e;
    }
    red[tid] = lsum; __syncthreads();
    for (int o = 128; o > 0; o >>= 1) { if (tid < o) red[tid] += red[tid + o]; __syncthreads(); }
    const float inv = 1.f / red[0];
    __syncthreads();

    float* wrow = w + ((long long)(b * HH + h) * SS_ + qi) * SS_;
    for (int j = tid; j < SS_; j += 256)
        wrow[j] = (j < n) ? sc[j] * inv : 0.f;
}

// ---------------- generic strided-batched tiled GEMM ----------------
// C[b,h] = act( A[b,h] @ B[b,h] + bias ) + res[b,h]
// Tiles: 64x64x16, 256 threads, 4x4 per thread. All dims divisible.
#define BM 64
#define BN 64
#define BKK 16
__global__ void gemm_kernel(const float* __restrict__ A, int lda, long long sAb, long long sAh,
                            const float* __restrict__ Bm, int ldb, long long sBb, long long sBh,
                            float* __restrict__ C, int ldc, long long sCb, long long sCh,
                            const float* __restrict__ bias,
                            const float* __restrict__ res, int ldr, long long sRb, long long sRh,
                            int K, int Hb, int act) {
    __shared__ float As[BM][BKK];
    __shared__ float Bs[BKK][BN];

    const int bz = blockIdx.z;
    const int b = bz / Hb, h = bz % Hb;
    A  += b * sAb + h * sAh;
    Bm += b * sBb + h * sBh;
    C  += b * sCb + h * sCh;
    if (res) res += b * sRb + h * sRh;

    const int row0 = blockIdx.y * BM;
    const int col0 = blockIdx.x * BN;
    const int tid = threadIdx.x;
    const int ty = tid >> 4, tx = tid & 15;

    float acc[4][4] = {};

    for (int k0 = 0; k0 < K; k0 += BKK) {
#pragma unroll
        for (int i = tid; i < BM * BKK; i += 256) {
            int r = i >> 4, c = i & 15;
            As[r][c] = A[(long long)(row0 + r) * lda + (k0 + c)];
        }
#pragma unroll
        for (int i = tid; i < BKK * BN; i += 256) {
            int r = i >> 6, c = i & 63;
            Bs[r][c] = Bm[(long long)(k0 + r) * ldb + (col0 + c)];
        }
        __syncthreads();
#pragma unroll
        for (int kk = 0; kk < BKK; kk++) {
            float a0 = As[ty * 4 + 0][kk];
            float a1 = As[ty * 4 + 1][kk];
            float a2 = As[ty * 4 + 2][kk];
            float a3 = As[ty * 4 + 3][kk];
            float b0 = Bs[kk][tx * 4 + 0];
            float b1 = Bs[kk][tx * 4 + 1];
            float b2 = Bs[kk][tx * 4 + 2];
            float b3 = Bs[kk][tx * 4 + 3];
            acc[0][0] += a0 * b0; acc[0][1] += a0 * b1; acc[0][2] += a0 * b2; acc[0][3] += a0 * b3;
            acc[1][0] += a1 * b0; acc[1][1] += a1 * b1; acc[1][2] += a1 * b2; acc[1][3] += a1 * b3;
            acc[2][0] += a2 * b0; acc[2][1] += a2 * b1; acc[2][2] += a2 * b2; acc[2][3] += a2 * b3;
            acc[3][0] += a3 * b0; acc[3][1] += a3 * b1; acc[3][2] += a3 * b2; acc[3][3] += a3 * b3;
        }
        __syncthreads();
    }

#pragma unroll
    for (int i = 0; i < 4; i++) {
        const int r = row0 + ty * 4 + i;
#pragma unroll
        for (int j = 0; j < 4; j++) {
            const int c = col0 + tx * 4 + j;
            float v = acc[i][j];
            if (bias) v += bias[c];
            if (act == 1) v = 0.5f * v * (1.f + erff(v * 0.70710678118654752f));
            if (res) v += res[(long long)r * ldr + c];
            C[(long long)r * ldc + c] = v;
        }
    }
}

// ---------------- host launch ----------------
extern "C" void kernel_launch(void* const* d_in, const int* in_sizes, int n_in,
                              void* d_out, int out_size) {
    const float* hidden  = (const float*)d_in[0];
    const int*   pos     = (const int*)  d_in[1];
    const float* wq      = (const float*)d_in[2];
    const float* wk      = (const float*)d_in[3];
    const float* wv      = (const float*)d_in[4];
    const float* wo      = (const float*)d_in[5];
    const float* ln1_g   = (const float*)d_in[6];
    const float* ln1_b   = (const float*)d_in[7];
    const float* ln2_g   = (const float*)d_in[8];
    const float* ln2_b   = (const float*)d_in[9];
    const float* fc_in_w = (const float*)d_in[10];
    const float* fc_in_b = (const float*)d_in[11];
    const float* fc_out_w= (const float*)d_in[12];
    const float* fc_out_b= (const float*)d_in[13];

    float* out0 = (float*)d_out;                               // [B,S,D]
    float* out1 = out0 + (long long)BB * SS_ * DD;             // [B,H,S,S]

    float *h, *q, *k, *v, *ctx, *res, *ffn;
    cudaGetSymbolAddress((void**)&h,   g_h);
    cudaGetSymbolAddress((void**)&q,   g_q);
    cudaGetSymbolAddress((void**)&k,   g_k);
    cudaGetSymbolAddress((void**)&v,   g_v);
    cudaGetSymbolAddress((void**)&ctx, g_ctx);
    cudaGetSymbolAddress((void**)&res, g_res);
    cudaGetSymbolAddress((void**)&ffn, g_ffn);

    // 1. LN1
    ln_kernel<<<ROWS, 256>>>(hidden, ln1_g, ln1_b, h);

    // 2. QKV projections: [4096,2048] @ [2048,2048]
    dim3 gQ(DD / BN, ROWS / BM, 1);
    gemm_kernel<<<gQ, 256>>>(h, DD, 0, 0, wq, DD, 0, 0, q, DD, 0, 0,
                             nullptr, nullptr, 0, 0, 0, DD, 1, 0);
    gemm_kernel<<<gQ, 256>>>(h, DD, 0, 0, wk, DD, 0, 0, k, DD, 0, 0,
                             nullptr, nullptr, 0, 0, 0, DD, 1, 0);
    gemm_kernel<<<gQ, 256>>>(h, DD, 0, 0, wv, DD, 0, 0, v, DD, 0, 0,
                             nullptr, nullptr, 0, 0, 0, DD, 1, 0);

    // 3. RoPE on q,k
    {
        long long total = (long long)ROWS * HH * 64;
        int blocks = (int)((total + 255) / 256);
        rope_kernel<<<blocks, 256>>>(q, k, pos);
    }

    // 4. scores + causal softmax -> attn_weights (out1)
    {
        dim3 gA(SS_, HH, BB);
        attn_kernel<<<gA, 256>>>(q, k, out1);
    }

    // 5. ctx = attn_weights @ v   (batched over B*H)
    {
        dim3 gV(DH_ / BN, SS_ / BM, BB * HH);
        gemm_kernel<<<gV, 256>>>(
            out1, SS_, (long long)HH * SS_ * SS_, (long long)SS_ * SS_,
            v,    DD,  (long long)SS_ * DD,       DH_,
            ctx,  DD,  (long long)SS_ * DD,       DH_,
            nullptr, nullptr, 0, 0, 0, SS_, HH, 0);
    }

    // 6. attn projection + residual: res = ctx @ wo + hidden
    gemm_kernel<<<gQ, 256>>>(ctx, DD, 0, 0, wo, DD, 0, 0, res, DD, 0, 0,
                             nullptr, hidden, DD, 0, 0, DD, 1, 0);

    // 7. LN2 -> h (h2)
    ln_kernel<<<ROWS, 256>>>(res, ln2_g, ln2_b, h);

    // 8. ffn = gelu(h2 @ fc_in + b)
    {
        dim3 gF1(FF_ / BN, ROWS / BM, 1);
        gemm_kernel<<<gF1, 256>>>(h, DD, 0, 0, fc_in_w, FF_, 0, 0, ffn, FF_, 0, 0,
                                  fc_in_b, nullptr, 0, 0, 0, DD, 1, 1);
    }

    // 9. out0 = ffn @ fc_out + b + h2
    {
        dim3 gF2(DD / BN, ROWS / BM, 1);
        gemm_kernel<<<gF2, 256>>>(ffn, FF_, 0, 0, fc_out_w, DD, 0, 0, out0, DD, 0, 0,
                                  fc_out_b, h, DD, 0, 0, FF_, 1, 0);
    }
}

// round 3
// speedup vs baseline: 1.9328x; 1.9328x over previous
#include <cuda_runtime.h>
#include <cuda_bf16.h>
#include <math.h>
#include <stdint.h>

// Problem dims (fixed)
#define BB 2
#define SS_ 2048
#define DD 2048
#define HH 16
#define DH_ 128
#define FF_ 8192
#define ROWS 4096            // B*S

// ---------------- scratch (device globals; no allocation) ----------------
__device__ float g_h   [(size_t)ROWS * DD];   // ln1 out, later h2
__device__ float g_q   [(size_t)ROWS * DD];
__device__ float g_k   [(size_t)ROWS * DD];
__device__ float g_v   [(size_t)ROWS * DD];
__device__ float g_ctx [(size_t)ROWS * DD];
__device__ float g_res [(size_t)ROWS * DD];
__device__ float g_ffn [(size_t)ROWS * FF_];

// bf16 hi/lo scratch. A buffers sized for attn weights (134M elems).
#define AMAX ((size_t)BB * HH * SS_ * SS_)
#define BMAX ((size_t)DD * FF_)
__device__ __nv_bfloat16 g_Ah[AMAX];
__device__ __nv_bfloat16 g_Al[AMAX];
__device__ __nv_bfloat16 g_Bh[BMAX];
__device__ __nv_bfloat16 g_Bl[BMAX];

__device__ __forceinline__ uint32_t smem_u32(const void* p) {
    uint32_t a;
    asm("{ .reg .u64 t; cvta.to.shared.u64 t, %1; cvt.u32.u64 %0, t; }" : "=r"(a) : "l"(p));
    return a;
}

#define LDMX4(r0, r1, r2, r3, addr) \
    asm volatile("ldmatrix.sync.aligned.m8n8.x4.shared.b16 {%0,%1,%2,%3}, [%4];" \
                 : "=r"(r0), "=r"(r1), "=r"(r2), "=r"(r3) : "r"(addr))

#define MMA16816(c, a, b0, b1) \
    asm volatile("mma.sync.aligned.m16n8k16.row.col.f32.bf16.bf16.f32 " \
                 "{%0,%1,%2,%3}, {%4,%5,%6,%7}, {%8,%9}, {%0,%1,%2,%3};" \
                 : "+f"((c)[0]), "+f"((c)[1]), "+f"((c)[2]), "+f"((c)[3]) \
                 : "r"((a)[0]), "r"((a)[1]), "r"((a)[2]), "r"((a)[3]), \
                   "r"(b0), "r"(b1))

// ===================== LayerNorm =====================
__global__ void ln_kernel(const float* __restrict__ x,
                          const float* __restrict__ g,
                          const float* __restrict__ b,
                          float* __restrict__ out) {
    __shared__ float red[256];
    const int row = blockIdx.x;
    const int tid = threadIdx.x;
    const float* xr = x + (long long)row * DD;

    float s = 0.f;
    for (int i = tid; i < DD; i += 256) s += xr[i];
    red[tid] = s; __syncthreads();
    for (int o = 128; o > 0; o >>= 1) { if (tid < o) red[tid] += red[tid + o]; __syncthreads(); }
    const float mean = red[0] * (1.f / DD);
    __syncthreads();

    float v = 0.f;
    for (int i = tid; i < DD; i += 256) { float d = xr[i] - mean; v += d * d; }
    red[tid] = v; __syncthreads();
    for (int o = 128; o > 0; o >>= 1) { if (tid < o) red[tid] += red[tid + o]; __syncthreads(); }
    const float rstd = rsqrtf(red[0] * (1.f / DD) + 1e-5f);

    float* orow = out + (long long)row * DD;
    for (int i = tid; i < DD; i += 256)
        orow[i] = (xr[i] - mean) * rstd * g[i] + b[i];
}

// ===================== RoPE =====================
__global__ void rope_kernel(float* __restrict__ q, float* __restrict__ k,
                            const int* __restrict__ pos) {
    long long idx = (long long)blockIdx.x * blockDim.x + threadIdx.x;
    const long long total = (long long)ROWS * HH * 64;
    if (idx >= total) return;
    const int i = (int)(idx & 63);
    long long t = idx >> 6;
    const int h = (int)(t % HH); t /= HH;
    const int s = (int)(t % SS_);
    const int b = (int)(t / SS_);

    const int p = pos[b * SS_ + s];
    const float inv = exp10f(-(float)i * (1.f / 16.f));
    const float ang = (float)p * inv;
    const float sn = sinf(ang), cs = cosf(ang);

    const long long base = ((((long long)b * SS_ + s) * HH + h) * DH_) + 2 * i;
    {
        float x0 = q[base], x1 = q[base + 1];
        q[base]     = x0 * cs - x1 * sn;
        q[base + 1] = x1 * cs + x0 * sn;
    }
    {
        float x0 = k[base], x1 = k[base + 1];
        k[base]     = x0 * cs - x1 * sn;
        k[base + 1] = x1 * cs + x0 * sn;
    }
}

// ===================== scores + causal softmax =====================
__global__ void attn_kernel(const float* __restrict__ q,
                            const float* __restrict__ k,
                            float* __restrict__ w) {
    __shared__ float qs[DH_];
    __shared__ float sc[SS_];
    __shared__ float red[256];

    const int qi = blockIdx.x, h = blockIdx.y, b = blockIdx.z;
    const int tid = threadIdx.x;

    const float* qrow = q + (((long long)b * SS_ + qi) * HH + h) * DH_;
    for (int i = tid; i < DH_; i += 256) qs[i] = qrow[i];
    __syncthreads();

    const int n = qi + 1;
    const float4* q4 = (const float4*)qs;

    float lmax = -1e30f;
    for (int j = tid; j < n; j += 256) {
        const float4* k4 = (const float4*)(k + (((long long)b * SS_ + j) * HH + h) * DH_);
        float d = 0.f;
#pragma unroll
        for (int c = 0; c < DH_ / 4; c++) {
            float4 kv = k4[c]; float4 qv = q4[c];
            d += kv.x * qv.x + kv.y * qv.y + kv.z * qv.z + kv.w * qv.w;
        }
        sc[j] = d;
        lmax = fmaxf(lmax, d);
    }
    red[tid] = lmax; __syncthreads();
    for (int o = 128; o > 0; o >>= 1) { if (tid < o) red[tid] = fmaxf(red[tid], red[tid + o]); __syncthreads(); }
    const float gmax = red[0];
    __syncthreads();

    float lsum = 0.f;
    for (int j = tid; j < n; j += 256) {
        float e = expf(sc[j] - gmax);
        sc[j] = e;
        lsum += e;
    }
    red[tid] = lsum; __syncthreads();
    for (int o = 128; o > 0; o >>= 1) { if (tid < o) red[tid] += red[tid + o]; __syncthreads(); }
    const float inv = 1.f / red[0];
    __syncthreads();

    float* wrow = w + ((long long)(b * HH + h) * SS_ + qi) * SS_;
    for (int j = tid; j < SS_; j += 256)
        wrow[j] = (j < n) ? sc[j] * inv : 0.f;
}

// ===================== decompose fp32 -> bf16 hi/lo (packed x4) =====================
__global__ void decomp4_kernel(const float* __restrict__ x,
                               __nv_bfloat16* __restrict__ hi,
                               __nv_bfloat16* __restrict__ lo) {
    long long i = (long long)blockIdx.x * 256 + threadIdx.x;
    float4 v = ((const float4*)x)[i];
    __nv_bfloat16 hx = __float2bfloat16(v.x);
    __nv_bfloat16 hy = __float2bfloat16(v.y);
    __nv_bfloat16 hz = __float2bfloat16(v.z);
    __nv_bfloat16 hw = __float2bfloat16(v.w);
    __nv_bfloat162* hi2 = (__nv_bfloat162*)hi;
    __nv_bfloat162* lo2 = (__nv_bfloat162*)lo;
    hi2[2 * i]     = __nv_bfloat162(hx, hy);
    hi2[2 * i + 1] = __nv_bfloat162(hz, hw);
    lo2[2 * i]     = __nv_bfloat162(__float2bfloat16(v.x - __bfloat162float(hx)),
                                    __float2bfloat16(v.y - __bfloat162float(hy)));
    lo2[2 * i + 1] = __nv_bfloat162(__float2bfloat16(v.z - __bfloat162float(hz)),
                                    __float2bfloat16(v.w - __bfloat162float(hw)));
}

// ===================== transpose+decompose weight [K,N] -> [N,K] hi/lo =====================
__global__ void wtrans_kernel(const float* __restrict__ w,
                              __nv_bfloat16* __restrict__ bh,
                              __nv_bfloat16* __restrict__ bl,
                              int Kdim, int Ndim) {
    __shared__ float t[32][33];
    const int k0 = blockIdx.x * 32, n0 = blockIdx.y * 32;
    const int tx = threadIdx.x & 31, ty = threadIdx.x >> 5;   // 256 threads: ty 0..7
#pragma unroll
    for (int i = 0; i < 32; i += 8)
        t[ty + i][tx] = w[(long long)(k0 + ty + i) * Ndim + n0 + tx];
    __syncthreads();
#pragma unroll
    for (int i = 0; i < 32; i += 8) {
        float v = t[tx][ty + i];
        long long o = (long long)(n0 + ty + i) * Kdim + k0 + tx;
        __nv_bfloat16 h = __float2bfloat16(v);
        bh[o] = h;
        bl[o] = __float2bfloat16(v - __bfloat162float(h));
    }
}

// ===================== transpose+decompose V [B,S,H,DH] -> [B,H,DH,S] hi/lo ==========
__global__ void vtrans_kernel(const float* __restrict__ v,
                              __nv_bfloat16* __restrict__ bh,
                              __nv_bfloat16* __restrict__ bl) {
    __shared__ float t[32][33];
    const int bh_i = blockIdx.z;
    const int b = bh_i >> 4, h = bh_i & 15;
    const int s0 = blockIdx.x * 32, d0 = blockIdx.y * 32;
    const int tx = threadIdx.x & 31, ty = threadIdx.x >> 5;
#pragma unroll
    for (int i = 0; i < 32; i += 8)
        t[ty + i][tx] = v[(((long long)b * SS_ + s0 + ty + i) * HH + h) * DH_ + d0 + tx];
    __syncthreads();
#pragma unroll
    for (int i = 0; i < 32; i += 8) {
        float val = t[tx][ty + i];
        long long o = ((long long)bh_i * DH_ + d0 + ty + i) * SS_ + s0 + tx;
        __nv_bfloat16 hh2 = __float2bfloat16(val);
        bh[o] = hh2;
        bl[o] = __float2bfloat16(val - __bfloat162float(hh2));
    }
}

// ===================== mma.sync bf16x3 GEMM =====================
// C[M,N] = act( A @ B^T + bias ) + res ; A[M,K], B[N,K] (both hi/lo bf16 K-major)
// Block tile 128x128, BK=32, 8 warps (2x4), warp tile 64x32.
#define SA 40   // padded smem row stride in bf16 elems (80B, 16B aligned, conflict-free ldmatrix)

__global__ __launch_bounds__(256) void mma_gemm(
        const __nv_bfloat16* __restrict__ Ah, const __nv_bfloat16* __restrict__ Al,
        int lda, long long sAb, long long sAhS,
        const __nv_bfloat16* __restrict__ Bh, const __nv_bfloat16* __restrict__ Bl,
        int ldb, long long sBb, long long sBhS,
        float* __restrict__ C, int ldc, long long sCb, long long sCh,
        const float* __restrict__ bias,
        const float* __restrict__ res, int ldr, long long sRb, long long sRh,
        int K, int Hb, int act) {
    __shared__ __nv_bfloat16 tAh[128 * SA];
    __shared__ __nv_bfloat16 tAl[128 * SA];
    __shared__ __nv_bfloat16 tBh[128 * SA];
    __shared__ __nv_bfloat16 tBl[128 * SA];

    const int tid = threadIdx.x;
    const int warp = tid >> 5, lane = tid & 31;
    const int wm = warp >> 2, wn = warp & 3;     // warp tile: rows wm*64, cols wn*32

    const int bz = blockIdx.z;
    const int b = bz / Hb, hh = bz % Hb;
    Ah += b * sAb + hh * sAhS;
    Al += b * sAb + hh * sAhS;
    Bh += b * sBb + hh * sBhS;
    Bl += b * sBb + hh * sBhS;
    C  += b * sCb + hh * sCh;
    if (res) res += b * sRb + hh * sRh;

    const int row0 = blockIdx.y * 128;
    const int col0 = blockIdx.x * 128;

    const uint32_t uAh = smem_u32(tAh);
    const uint32_t uAl = smem_u32(tAl);
    const uint32_t uBh = smem_u32(tBh);
    const uint32_t uBl = smem_u32(tBl);

    float acc[4][4][4] = {};

    // per-thread load coords: thread handles rows (tid>>2), 16B chunk (tid&3), x2 (p)
    const int lr0 = tid >> 2, lc = (tid & 3) * 8;

    // ldmatrix smem addresses (element offsets), fixed per thread
    // A-style: row = base + (lane&15), colhalf = (lane>>4)*8
    const int a_r = lane & 15, a_c = (lane >> 4) * 8;
    // B-style: row = base + ((lane>>4)<<3) + (lane&7), col = ((lane>>3)&1)*8
    const int b_r = ((lane >> 4) << 3) + (lane & 7), b_c = ((lane >> 3) & 1) * 8;

    const int nch = K / 32;
    for (int ch = 0; ch < nch; ch++) {
        const int kb = ch * 32;
#pragma unroll
        for (int p = 0; p < 2; p++) {
            const int r = lr0 + p * 64;
            const long long ga = (long long)(row0 + r) * lda + kb + lc;
            const long long gb = (long long)(col0 + r) * ldb + kb + lc;
            const uint32_t so = (uint32_t)(r * SA + lc) * 2;
            *(uint4*)((char*)tAh + so) = *(const uint4*)(Ah + ga);
            *(uint4*)((char*)tAl + so) = *(const uint4*)(Al + ga);
            *(uint4*)((char*)tBh + so) = *(const uint4*)(Bh + gb);
            *(uint4*)((char*)tBl + so) = *(const uint4*)(Bl + gb);
        }
        __syncthreads();

#pragma unroll
        for (int ks = 0; ks < 2; ks++) {
            const int kc = ks * 16;
            uint32_t af[4][4], fbh[2][4], fbl[2][4];
#pragma unroll
            for (int nb = 0; nb < 2; nb++) {
                const uint32_t off = (uint32_t)((wn * 32 + nb * 16 + b_r) * SA + kc + b_c) * 2;
                LDMX4(fbh[nb][0], fbh[nb][1], fbh[nb][2], fbh[nb][3], uBh + off);
                LDMX4(fbl[nb][0], fbl[nb][1], fbl[nb][2], fbl[nb][3], uBl + off);
            }
#pragma unroll
            for (int mi = 0; mi < 4; mi++) {
                const uint32_t off = (uint32_t)((wm * 64 + mi * 16 + a_r) * SA + kc + a_c) * 2;
                LDMX4(af[mi][0], af[mi][1], af[mi][2], af[mi][3], uAh + off);
            }
            // Ah*Bh and Ah*Bl
#pragma unroll
            for (int mi = 0; mi < 4; mi++)
#pragma unroll
                for (int ni = 0; ni < 4; ni++) {
                    MMA16816(acc[mi][ni], af[mi], fbh[ni >> 1][(ni & 1) * 2], fbh[ni >> 1][(ni & 1) * 2 + 1]);
                    MMA16816(acc[mi][ni], af[mi], fbl[ni >> 1][(ni & 1) * 2], fbl[ni >> 1][(ni & 1) * 2 + 1]);
                }
            // Al*Bh (reuse af regs)
#pragma unroll
            for (int mi = 0; mi < 4; mi++) {
                const uint32_t off = (uint32_t)((wm * 64 + mi * 16 + a_r) * SA + kc + a_c) * 2;
                LDMX4(af[mi][0], af[mi][1], af[mi][2], af[mi][3], uAl + off);
            }
#pragma unroll
            for (int mi = 0; mi < 4; mi++)
#pragma unroll
                for (int ni = 0; ni < 4; ni++)
                    MMA16816(acc[mi][ni], af[mi], fbh[ni >> 1][(ni & 1) * 2], fbh[ni >> 1][(ni & 1) * 2 + 1]);
        }
        __syncthreads();
    }

    // epilogue: c frag: rows lane>>2 (+8), cols (lane&3)*2
#pragma unroll
    for (int mi = 0; mi < 4; mi++) {
#pragma unroll
        for (int ni = 0; ni < 4; ni++) {
#pragma unroll
            for (int half = 0; half < 2; half++) {
                const long long r = row0 + wm * 64 + mi * 16 + (lane >> 2) + half * 8;
                const int cc = col0 + wn * 32 + ni * 8 + (lane & 3) * 2;
                float x = acc[mi][ni][half * 2];
                float y = acc[mi][ni][half * 2 + 1];
                if (bias) { x += bias[cc]; y += bias[cc + 1]; }
                if (act == 1) {
                    x = 0.5f * x * (1.f + erff(x * 0.70710678118654752f));
                    y = 0.5f * y * (1.f + erff(y * 0.70710678118654752f));
                }
                if (res) {
                    x += res[r * ldr + cc];
                    y += res[r * ldr + cc + 1];
                }
                *(float2*)(C + r * ldc + cc) = make_float2(x, y);
            }
        }
    }
}

// ===================== host launch =====================
extern "C" void kernel_launch(void* const* d_in, const int* in_sizes, int n_in,
                              void* d_out, int out_size) {
    const float* hidden  = (const float*)d_in[0];
    const int*   pos     = (const int*)  d_in[1];
    const float* wq      = (const float*)d_in[2];
    const float* wk      = (const float*)d_in[3];
    const float* wv      = (const float*)d_in[4];
    const float* wo      = (const float*)d_in[5];
    const float* ln1_g   = (const float*)d_in[6];
    const float* ln1_b   = (const float*)d_in[7];
    const float* ln2_g   = (const float*)d_in[8];
    const float* ln2_b   = (const float*)d_in[9];
    const float* fc_in_w = (const float*)d_in[10];
    const float* fc_in_b = (const float*)d_in[11];
    const float* fc_out_w= (const float*)d_in[12];
    const float* fc_out_b= (const float*)d_in[13];

    float* out0 = (float*)d_out;                               // [B,S,D]
    float* out1 = out0 + (long long)BB * SS_ * DD;             // [B,H,S,S]

    float *h, *q, *k, *v, *ctx, *res, *ffn;
    __nv_bfloat16 *Ah, *Al, *Bh, *Bl;
    cudaGetSymbolAddress((void**)&h,   g_h);
    cudaGetSymbolAddress((void**)&q,   g_q);
    cudaGetSymbolAddress((void**)&k,   g_k);
    cudaGetSymbolAddress((void**)&v,   g_v);
    cudaGetSymbolAddress((void**)&ctx, g_ctx);
    cudaGetSymbolAddress((void**)&res, g_res);
    cudaGetSymbolAddress((void**)&ffn, g_ffn);
    cudaGetSymbolAddress((void**)&Ah,  g_Ah);
    cudaGetSymbolAddress((void**)&Al,  g_Al);
    cudaGetSymbolAddress((void**)&Bh,  g_Bh);
    cudaGetSymbolAddress((void**)&Bl,  g_Bl);

    // 1. LN1
    ln_kernel<<<ROWS, 256>>>(hidden, ln1_g, ln1_b, h);

    // 2. decompose h; transpose+decompose wq/wk/wv; QKV GEMMs
    decomp4_kernel<<<(int)((long long)ROWS * DD / 4 / 256), 256>>>(h, Ah, Al);
    dim3 gQ(DD / 128, ROWS / 128, 1);
    dim3 gW(DD / 32, DD / 32);
    wtrans_kernel<<<gW, 256>>>(wq, Bh, Bl, DD, DD);
    mma_gemm<<<gQ, 256>>>(Ah, Al, DD, 0, 0, Bh, Bl, DD, 0, 0,
                          q, DD, 0, 0, nullptr, nullptr, 0, 0, 0, DD, 1, 0);
    wtrans_kernel<<<gW, 256>>>(wk, Bh, Bl, DD, DD);
    mma_gemm<<<gQ, 256>>>(Ah, Al, DD, 0, 0, Bh, Bl, DD, 0, 0,
                          k, DD, 0, 0, nullptr, nullptr, 0, 0, 0, DD, 1, 0);
    wtrans_kernel<<<gW, 256>>>(wv, Bh, Bl, DD, DD);
    mma_gemm<<<gQ, 256>>>(Ah, Al, DD, 0, 0, Bh, Bl, DD, 0, 0,
                          v, DD, 0, 0, nullptr, nullptr, 0, 0, 0, DD, 1, 0);

    // 3. RoPE
    {
        long long total = (long long)ROWS * HH * 64;
        rope_kernel<<<(int)((total + 255) / 256), 256>>>(q, k, pos);
    }

    // 4. scores + causal softmax -> attn_weights (out1)
    {
        dim3 gA(SS_, HH, BB);
        attn_kernel<<<gA, 256>>>(q, k, out1);
    }

    // 5. ctx = attn_weights @ v  (batched over B*H, tensor cores)
    decomp4_kernel<<<(int)(AMAX / 4 / 256), 256>>>(out1, Ah, Al);
    {
        dim3 gVT(SS_ / 32, DH_ / 32, BB * HH);
        vtrans_kernel<<<gVT, 256>>>(v, Bh, Bl);
        dim3 gV(DH_ / 128, SS_ / 128, BB * HH);
        mma_gemm<<<gV, 256>>>(
            Ah, Al, SS_, (long long)HH * SS_ * SS_, (long long)SS_ * SS_,
            Bh, Bl, SS_, (long long)HH * DH_ * SS_, (long long)DH_ * SS_,
            ctx, DD, (long long)SS_ * DD, DH_,
            nullptr, nullptr, 0, 0, 0, SS_, HH, 0);
    }

    // 6. res = ctx @ wo + hidden
    decomp4_kernel<<<(int)((long long)ROWS * DD / 4 / 256), 256>>>(ctx, Ah, Al);
    wtrans_kernel<<<gW, 256>>>(wo, Bh, Bl, DD, DD);
    mma_gemm<<<gQ, 256>>>(Ah, Al, DD, 0, 0, Bh, Bl, DD, 0, 0,
                          res, DD, 0, 0, nullptr, hidden, DD, 0, 0, DD, 1, 0);

    // 7. LN2 -> h (h2)
    ln_kernel<<<ROWS, 256>>>(res, ln2_g, ln2_b, h);

    // 8. ffn = gelu(h2 @ fc_in + b)
    decomp4_kernel<<<(int)((long long)ROWS * DD / 4 / 256), 256>>>(h, Ah, Al);
    {
        dim3 gW1(DD / 32, FF_ / 32);
        wtrans_kernel<<<gW1, 256>>>(fc_in_w, Bh, Bl, DD, FF_);
        dim3 gF1(FF_ / 128, ROWS / 128, 1);
        mma_gemm<<<gF1, 256>>>(Ah, Al, DD, 0, 0, Bh, Bl, DD, 0, 0,
                               ffn, FF_, 0, 0, fc_in_b, nullptr, 0, 0, 0, DD, 1, 1);
    }

    // 9. out0 = ffn @ fc_out + b + h2
    decomp4_kernel<<<(int)((long long)ROWS * FF_ / 4 / 256), 256>>>(ffn, Ah, Al);
    {
        dim3 gW2(FF_ / 32, DD / 32);
        wtrans_kernel<<<gW2, 256>>>(fc_out_w, Bh, Bl, FF_, DD);
        dim3 gF2(DD / 128, ROWS / 128, 1);
        mma_gemm<<<gF2, 256>>>(Ah, Al, FF_, 0, 0, Bh, Bl, FF_, 0, 0,
                               out0, DD, 0, 0, fc_out_b, h, DD, 0, 0, FF_, 1, 0);
    }
}

// round 4
// speedup vs baseline: 5.2236x; 2.7025x over previous
#include <cuda_runtime.h>
#include <cuda_bf16.h>
#include <math.h>
#include <stdint.h>

// Problem dims (fixed)
#define BB 2
#define SS_ 2048
#define DD 2048
#define HH 16
#define DH_ 128
#define FF_ 8192
#define ROWS 4096            // B*S

// ---------------- scratch ----------------
__device__ float g_h   [(size_t)ROWS * DD];
__device__ float g_q   [(size_t)ROWS * DD];
__device__ float g_k   [(size_t)ROWS * DD];
__device__ float g_v   [(size_t)ROWS * DD];
__device__ float g_ctx [(size_t)ROWS * DD];
__device__ float g_res [(size_t)ROWS * DD];
__device__ float g_ffn [(size_t)ROWS * FF_];

#define AMAX ((size_t)BB * HH * SS_ * SS_)
#define BMAX ((size_t)DD * FF_)
__device__ __nv_bfloat16 g_Ah[AMAX];
__device__ __nv_bfloat16 g_Al[AMAX];
__device__ __nv_bfloat16 g_Bh[BMAX];
__device__ __nv_bfloat16 g_Bl[BMAX];

__device__ __forceinline__ uint32_t smem_u32(const void* p) {
    uint32_t a;
    asm("{ .reg .u64 t; cvta.to.shared.u64 t, %1; cvt.u32.u64 %0, t; }" : "=r"(a) : "l"(p));
    return a;
}

#define LDMX4(r0, r1, r2, r3, addr) \
    asm volatile("ldmatrix.sync.aligned.m8n8.x4.shared.b16 {%0,%1,%2,%3}, [%4];" \
                 : "=r"(r0), "=r"(r1), "=r"(r2), "=r"(r3) : "r"(addr))

#define MMA16816(c, a, b0, b1) \
    asm volatile("mma.sync.aligned.m16n8k16.row.col.f32.bf16.bf16.f32 " \
                 "{%0,%1,%2,%3}, {%4,%5,%6,%7}, {%8,%9}, {%0,%1,%2,%3};" \
                 : "+f"((c)[0]), "+f"((c)[1]), "+f"((c)[2]), "+f"((c)[3]) \
                 : "r"((a)[0]), "r"((a)[1]), "r"((a)[2]), "r"((a)[3]), \
                   "r"(b0), "r"(b1))

#define CP16(dst, src) \
    asm volatile("cp.async.cg.shared.global [%0], [%1], 16;" :: "r"(dst), "l"(src))
#define CP_COMMIT() asm volatile("cp.async.commit_group;" ::: "memory")
#define CP_WAIT1()  asm volatile("cp.async.wait_group 1;" ::: "memory")

// ===================== LayerNorm (row cached in smem) =====================
__global__ void ln_kernel(const float* __restrict__ x,
                          const float* __restrict__ g,
                          const float* __restrict__ b,
                          float* __restrict__ out) {
    __shared__ float xs[DD];
    __shared__ float red[256];
    const int row = blockIdx.x;
    const int tid = threadIdx.x;
    const float* xr = x + (long long)row * DD;

    float s = 0.f;
    for (int i = tid; i < DD; i += 256) { float t = xr[i]; xs[i] = t; s += t; }
    red[tid] = s; __syncthreads();
    for (int o = 128; o > 0; o >>= 1) { if (tid < o) red[tid] += red[tid + o]; __syncthreads(); }
    const float mean = red[0] * (1.f / DD);
    __syncthreads();

    float v = 0.f;
    for (int i = tid; i < DD; i += 256) { float d = xs[i] - mean; v += d * d; }
    red[tid] = v; __syncthreads();
    for (int o = 128; o > 0; o >>= 1) { if (tid < o) red[tid] += red[tid + o]; __syncthreads(); }
    const float rstd = rsqrtf(red[0] * (1.f / DD) + 1e-5f);

    float* orow = out + (long long)row * DD;
    for (int i = tid; i < DD; i += 256)
        orow[i] = (xs[i] - mean) * rstd * g[i] + b[i];
}

// ===================== RoPE =====================
__global__ void rope_kernel(float* __restrict__ q, float* __restrict__ k,
                            const int* __restrict__ pos) {
    long long idx = (long long)blockIdx.x * blockDim.x + threadIdx.x;
    const long long total = (long long)ROWS * HH * 64;
    if (idx >= total) return;
    const int i = (int)(idx & 63);
    long long t = idx >> 6;
    const int h = (int)(t % HH); t /= HH;
    const int s = (int)(t % SS_);
    const int b = (int)(t / SS_);

    const int p = pos[b * SS_ + s];
    const float inv = exp10f(-(float)i * (1.f / 16.f));
    const float ang = (float)p * inv;
    const float sn = sinf(ang), cs = cosf(ang);

    const long long base = ((((long long)b * SS_ + s) * HH + h) * DH_) + 2 * i;
    {
        float x0 = q[base], x1 = q[base + 1];
        q[base]     = x0 * cs - x1 * sn;
        q[base + 1] = x1 * cs + x0 * sn;
    }
    {
        float x0 = k[base], x1 = k[base + 1];
        k[base]     = x0 * cs - x1 * sn;
        k[base + 1] = x1 * cs + x0 * sn;
    }
}

// ===================== row softmax in place (causal) =====================
__global__ void softmax_kernel(float* __restrict__ w) {
    __shared__ float sc[SS_];
    __shared__ float red[256];
    const int qi = blockIdx.x, h = blockIdx.y, b = blockIdx.z;
    const int tid = threadIdx.x;
    float* wrow = w + ((long long)(b * HH + h) * SS_ + qi) * SS_;
    const int n = qi + 1;

    float lmax = -1e30f;
    for (int j = tid; j < n; j += 256) { float t = wrow[j]; sc[j] = t; lmax = fmaxf(lmax, t); }
    red[tid] = lmax; __syncthreads();
    for (int o = 128; o > 0; o >>= 1) { if (tid < o) red[tid] = fmaxf(red[tid], red[tid + o]); __syncthreads(); }
    const float gmax = red[0];
    __syncthreads();

    float lsum = 0.f;
    for (int j = tid; j < n; j += 256) { float e = expf(sc[j] - gmax); sc[j] = e; lsum += e; }
    red[tid] = lsum; __syncthreads();
    for (int o = 128; o > 0; o >>= 1) { if (tid < o) red[tid] += red[tid + o]; __syncthreads(); }
    const float inv = 1.f / red[0];
    __syncthreads();

    for (int j = tid; j < SS_; j += 256)
        wrow[j] = (j < n) ? sc[j] * inv : 0.f;
}

// ===================== decompose fp32 -> bf16 hi/lo =====================
__global__ void decomp4_kernel(const float* __restrict__ x,
                               __nv_bfloat16* __restrict__ hi,
                               __nv_bfloat16* __restrict__ lo) {
    long long i = (long long)blockIdx.x * 256 + threadIdx.x;
    float4 v = ((const float4*)x)[i];
    __nv_bfloat16 hx = __float2bfloat16(v.x);
    __nv_bfloat16 hy = __float2bfloat16(v.y);
    __nv_bfloat16 hz = __float2bfloat16(v.z);
    __nv_bfloat16 hw = __float2bfloat16(v.w);
    __nv_bfloat162* hi2 = (__nv_bfloat162*)hi;
    __nv_bfloat162* lo2 = (__nv_bfloat162*)lo;
    hi2[2 * i]     = __nv_bfloat162(hx, hy);
    hi2[2 * i + 1] = __nv_bfloat162(hz, hw);
    lo2[2 * i]     = __nv_bfloat162(__float2bfloat16(v.x - __bfloat162float(hx)),
                                    __float2bfloat16(v.y - __bfloat162float(hy)));
    lo2[2 * i + 1] = __nv_bfloat162(__float2bfloat16(v.z - __bfloat162float(hz)),
                                    __float2bfloat16(v.w - __bfloat162float(hw)));
}

// ===================== transpose+decompose weight [K,N] -> [N,K] =====================
__global__ void wtrans_kernel(const float* __restrict__ w,
                              __nv_bfloat16* __restrict__ bh,
                              __nv_bfloat16* __restrict__ bl,
                              int Kdim, int Ndim) {
    __shared__ float t[32][33];
    const int k0 = blockIdx.x * 32, n0 = blockIdx.y * 32;
    const int tx = threadIdx.x & 31, ty = threadIdx.x >> 5;
#pragma unroll
    for (int i = 0; i < 32; i += 8)
        t[ty + i][tx] = w[(long long)(k0 + ty + i) * Ndim + n0 + tx];
    __syncthreads();
#pragma unroll
    for (int i = 0; i < 32; i += 8) {
        float v = t[tx][ty + i];
        long long o = (long long)(n0 + ty + i) * Kdim + k0 + tx;
        __nv_bfloat16 h = __float2bfloat16(v);
        bh[o] = h;
        bl[o] = __float2bfloat16(v - __bfloat162float(h));
    }
}

// ===================== transpose+decompose V [B,S,H,DH] -> [B,H,DH,S] ==========
__global__ void vtrans_kernel(const float* __restrict__ v,
                              __nv_bfloat16* __restrict__ bh,
                              __nv_bfloat16* __restrict__ bl) {
    __shared__ float t[32][33];
    const int bh_i = blockIdx.z;
    const int b = bh_i >> 4, h = bh_i & 15;
    const int s0 = blockIdx.x * 32, d0 = blockIdx.y * 32;
    const int tx = threadIdx.x & 31, ty = threadIdx.x >> 5;
#pragma unroll
    for (int i = 0; i < 32; i += 8)
        t[ty + i][tx] = v[(((long long)b * SS_ + s0 + ty + i) * HH + h) * DH_ + d0 + tx];
    __syncthreads();
#pragma unroll
    for (int i = 0; i < 32; i += 8) {
        float val = t[tx][ty + i];
        long long o = ((long long)bh_i * DH_ + d0 + ty + i) * SS_ + s0 + tx;
        __nv_bfloat16 hh2 = __float2bfloat16(val);
        bh[o] = hh2;
        bl[o] = __float2bfloat16(val - __bfloat162float(hh2));
    }
}

// ===================== pipelined mma.sync bf16x3 GEMM =====================
// C[M,N] = act( A @ B^T + bias ) + res ; A[M,K], B[N,K] hi/lo bf16 K-major
// 128x128 block, BK=32, 8 warps, cp.async 3-stage pipeline.
// causal: 0=none, 1=skip blocks with col0>row0+127 (scores), 2=limit K to row0+128 (attn·V)
#define SA 40
#define STAGES 3
#define TILEB (128 * SA * 2)
#define STAGEB (4 * TILEB)
#define GSMEM (STAGES * STAGEB)

__global__ __launch_bounds__(256) void mma_gemm(
        const __nv_bfloat16* __restrict__ Ah, const __nv_bfloat16* __restrict__ Al,
        int lda, long long sAb, long long sAhS,
        const __nv_bfloat16* __restrict__ Bh, const __nv_bfloat16* __restrict__ Bl,
        int ldb, long long sBb, long long sBhS,
        float* __restrict__ C, int ldc, long long sCb, long long sCh,
        const float* __restrict__ bias,
        const float* __restrict__ res, int ldr, long long sRb, long long sRh,
        int K, int Hb, int act, int causal) {
    extern __shared__ char dsm[];

    const int row0 = blockIdx.y * 128;
    const int col0 = blockIdx.x * 128;
    if (causal == 1 && col0 > row0 + 127) return;

    const int tid = threadIdx.x;
    const int warp = tid >> 5, lane = tid & 31;
    const int wm = warp >> 2, wn = warp & 3;

    const int bz = blockIdx.z;
    const int b = bz / Hb, hh = bz % Hb;
    Ah += b * sAb + hh * sAhS;
    Al += b * sAb + hh * sAhS;
    Bh += b * sBb + hh * sBhS;
    Bl += b * sBb + hh * sBhS;
    C  += b * sCb + hh * sCh;
    if (res) res += b * sRb + hh * sRh;

    const uint32_t u0 = smem_u32(dsm);

    float acc[4][4][4] = {};

    const int lr0 = tid >> 2, lc = (tid & 3) * 8;
    const int a_r = lane & 15, a_c = (lane >> 4) * 8;
    const int b_r = ((lane >> 4) << 3) + (lane & 7), b_c = ((lane >> 3) & 1) * 8;

    int nch = K / 32;
    if (causal == 2) { int lim = (row0 + 128) / 32; if (lim < nch) nch = lim; }

    auto load_chunk = [&](int ch, int st) {
        const int kb = ch * 32;
        const uint32_t base = u0 + st * STAGEB;
#pragma unroll
        for (int p = 0; p < 2; p++) {
            const int r = lr0 + p * 64;
            const long long ga = (long long)(row0 + r) * lda + kb + lc;
            const long long gb = (long long)(col0 + r) * ldb + kb + lc;
            const uint32_t so = (uint32_t)(r * SA + lc) * 2;
            CP16(base + so,             Ah + ga);
            CP16(base + TILEB + so,     Al + ga);
            CP16(base + 2 * TILEB + so, Bh + gb);
            CP16(base + 3 * TILEB + so, Bl + gb);
        }
    };

    for (int ch = 0; ch < STAGES - 1; ch++) {
        if (ch < nch) load_chunk(ch, ch);
        CP_COMMIT();
    }

    for (int ch = 0; ch < nch; ch++) {
        CP_WAIT1();
        __syncthreads();
        const int nx = ch + STAGES - 1;
        if (nx < nch) load_chunk(nx, nx % STAGES);
        CP_COMMIT();

        const uint32_t base = u0 + (ch % STAGES) * STAGEB;
        const uint32_t uAh = base, uAl = base + TILEB;
        const uint32_t uBh = base + 2 * TILEB, uBl = base + 3 * TILEB;

#pragma unroll
        for (int ks = 0; ks < 2; ks++) {
            const int kc = ks * 16;
            uint32_t af[4][4], fbh[2][4], fbl[2][4];
#pragma unroll
            for (int nb = 0; nb < 2; nb++) {
                const uint32_t off = (uint32_t)((wn * 32 + nb * 16 + b_r) * SA + kc + b_c) * 2;
                LDMX4(fbh[nb][0], fbh[nb][1], fbh[nb][2], fbh[nb][3], uBh + off);
                LDMX4(fbl[nb][0], fbl[nb][1], fbl[nb][2], fbl[nb][3], uBl + off);
            }
#pragma unroll
            for (int mi = 0; mi < 4; mi++) {
                const uint32_t off = (uint32_t)((wm * 64 + mi * 16 + a_r) * SA + kc + a_c) * 2;
                LDMX4(af[mi][0], af[mi][1], af[mi][2], af[mi][3], uAh + off);
            }
#pragma unroll
            for (int mi = 0; mi < 4; mi++)
#pragma unroll
                for (int ni = 0; ni < 4; ni++) {
                    MMA16816(acc[mi][ni], af[mi], fbh[ni >> 1][(ni & 1) * 2], fbh[ni >> 1][(ni & 1) * 2 + 1]);
                    MMA16816(acc[mi][ni], af[mi], fbl[ni >> 1][(ni & 1) * 2], fbl[ni >> 1][(ni & 1) * 2 + 1]);
                }
#pragma unroll
            for (int mi = 0; mi < 4; mi++) {
                const uint32_t off = (uint32_t)((wm * 64 + mi * 16 + a_r) * SA + kc + a_c) * 2;
                LDMX4(af[mi][0], af[mi][1], af[mi][2], af[mi][3], uAl + off);
            }
#pragma unroll
            for (int mi = 0; mi < 4; mi++)
#pragma unroll
                for (int ni = 0; ni < 4; ni++)
                    MMA16816(acc[mi][ni], af[mi], fbh[ni >> 1][(ni & 1) * 2], fbh[ni >> 1][(ni & 1) * 2 + 1]);
        }
        __syncthreads();
    }

    // epilogue
#pragma unroll
    for (int mi = 0; mi < 4; mi++) {
#pragma unroll
        for (int ni = 0; ni < 4; ni++) {
#pragma unroll
            for (int half = 0; half < 2; half++) {
                const long long r = row0 + wm * 64 + mi * 16 + (lane >> 2) + half * 8;
                const int cc = col0 + wn * 32 + ni * 8 + (lane & 3) * 2;
                float x = acc[mi][ni][half * 2];
                float y = acc[mi][ni][half * 2 + 1];
                if (bias) { x += bias[cc]; y += bias[cc + 1]; }
                if (act == 1) {
                    x = 0.5f * x * (1.f + erff(x * 0.70710678118654752f));
                    y = 0.5f * y * (1.f + erff(y * 0.70710678118654752f));
                }
                if (res) {
                    x += res[r * ldr + cc];
                    y += res[r * ldr + cc + 1];
                }
                *(float2*)(C + r * ldc + cc) = make_float2(x, y);
            }
        }
    }
}

// ===================== host launch =====================
extern "C" void kernel_launch(void* const* d_in, const int* in_sizes, int n_in,
                              void* d_out, int out_size) {
    const float* hidden  = (const float*)d_in[0];
    const int*   pos     = (const int*)  d_in[1];
    const float* wq      = (const float*)d_in[2];
    const float* wk      = (const float*)d_in[3];
    const float* wv      = (const float*)d_in[4];
    const float* wo      = (const float*)d_in[5];
    const float* ln1_g   = (const float*)d_in[6];
    const float* ln1_b   = (const float*)d_in[7];
    const float* ln2_g   = (const float*)d_in[8];
    const float* ln2_b   = (const float*)d_in[9];
    const float* fc_in_w = (const float*)d_in[10];
    const float* fc_in_b = (const float*)d_in[11];
    const float* fc_out_w= (const float*)d_in[12];
    const float* fc_out_b= (const float*)d_in[13];

    float* out0 = (float*)d_out;                               // [B,S,D]
    float* out1 = out0 + (long long)BB * SS_ * DD;             // [B,H,S,S]

    float *h, *q, *k, *v, *ctx, *res, *ffn;
    __nv_bfloat16 *Ah, *Al, *Bh, *Bl;
    cudaGetSymbolAddress((void**)&h,   g_h);
    cudaGetSymbolAddress((void**)&q,   g_q);
    cudaGetSymbolAddress((void**)&k,   g_k);
    cudaGetSymbolAddress((void**)&v,   g_v);
    cudaGetSymbolAddress((void**)&ctx, g_ctx);
    cudaGetSymbolAddress((void**)&res, g_res);
    cudaGetSymbolAddress((void**)&ffn, g_ffn);
    cudaGetSymbolAddress((void**)&Ah,  g_Ah);
    cudaGetSymbolAddress((void**)&Al,  g_Al);
    cudaGetSymbolAddress((void**)&Bh,  g_Bh);
    cudaGetSymbolAddress((void**)&Bl,  g_Bl);

    cudaFuncSetAttribute(mma_gemm, cudaFuncAttributeMaxDynamicSharedMemorySize, GSMEM);

    // 1. LN1
    ln_kernel<<<ROWS, 256>>>(hidden, ln1_g, ln1_b, h);

    // 2. QKV
    decomp4_kernel<<<(int)((long long)ROWS * DD / 4 / 256), 256>>>(h, Ah, Al);
    dim3 gQ(DD / 128, ROWS / 128, 1);
    dim3 gW(DD / 32, DD / 32);
    wtrans_kernel<<<gW, 256>>>(wq, Bh, Bl, DD, DD);
    mma_gemm<<<gQ, 256, GSMEM>>>(Ah, Al, DD, 0, 0, Bh, Bl, DD, 0, 0,
                                 q, DD, 0, 0, nullptr, nullptr, 0, 0, 0, DD, 1, 0, 0);
    wtrans_kernel<<<gW, 256>>>(wk, Bh, Bl, DD, DD);
    mma_gemm<<<gQ, 256, GSMEM>>>(Ah, Al, DD, 0, 0, Bh, Bl, DD, 0, 0,
                                 k, DD, 0, 0, nullptr, nullptr, 0, 0, 0, DD, 1, 0, 0);
    wtrans_kernel<<<gW, 256>>>(wv, Bh, Bl, DD, DD);
    mma_gemm<<<gQ, 256, GSMEM>>>(Ah, Al, DD, 0, 0, Bh, Bl, DD, 0, 0,
                                 v, DD, 0, 0, nullptr, nullptr, 0, 0, 0, DD, 1, 0, 0);

    // 3. RoPE
    {
        long long total = (long long)ROWS * HH * 64;
        rope_kernel<<<(int)((total + 255) / 256), 256>>>(q, k, pos);
    }

    // 4. scores = q @ k^T per head (causal blocks only) -> out1
    decomp4_kernel<<<(int)((long long)ROWS * DD / 4 / 256), 256>>>(q, Ah, Al);
    decomp4_kernel<<<(int)((long long)ROWS * DD / 4 / 256), 256>>>(k, Bh, Bl);
    {
        dim3 gS(SS_ / 128, SS_ / 128, BB * HH);
        mma_gemm<<<gS, 256, GSMEM>>>(
            Ah, Al, DD, (long long)SS_ * DD, DH_,
            Bh, Bl, DD, (long long)SS_ * DD, DH_,
            out1, SS_, (long long)HH * SS_ * SS_, (long long)SS_ * SS_,
            nullptr, nullptr, 0, 0, 0, DH_, HH, 0, 1);
    }

    // 5. softmax in place
    {
        dim3 gA(SS_, HH, BB);
        softmax_kernel<<<gA, 256>>>(out1);
    }

    // 6. ctx = attn_weights @ v (causal K limit)
    decomp4_kernel<<<(int)(AMAX / 4 / 256), 256>>>(out1, Ah, Al);
    {
        dim3 gVT(SS_ / 32, DH_ / 32, BB * HH);
        vtrans_kernel<<<gVT, 256>>>(v, Bh, Bl);
        dim3 gV(DH_ / 128, SS_ / 128, BB * HH);
        mma_gemm<<<gV, 256, GSMEM>>>(
            Ah, Al, SS_, (long long)HH * SS_ * SS_, (long long)SS_ * SS_,
            Bh, Bl, SS_, (long long)HH * DH_ * SS_, (long long)DH_ * SS_,
            ctx, DD, (long long)SS_ * DD, DH_,
            nullptr, nullptr, 0, 0, 0, SS_, HH, 0, 2);
    }

    // 7. res = ctx @ wo + hidden
    decomp4_kernel<<<(int)((long long)ROWS * DD / 4 / 256), 256>>>(ctx, Ah, Al);
    wtrans_kernel<<<gW, 256>>>(wo, Bh, Bl, DD, DD);
    mma_gemm<<<gQ, 256, GSMEM>>>(Ah, Al, DD, 0, 0, Bh, Bl, DD, 0, 0,
                                 res, DD, 0, 0, nullptr, hidden, DD, 0, 0, DD, 1, 0, 0);

    // 8. LN2
    ln_kernel<<<ROWS, 256>>>(res, ln2_g, ln2_b, h);

    // 9. ffn = gelu(h2 @ fc_in + b)
    decomp4_kernel<<<(int)((long long)ROWS * DD / 4 / 256), 256>>>(h, Ah, Al);
    {
        dim3 gW1(DD / 32, FF_ / 32);
        wtrans_kernel<<<gW1, 256>>>(fc_in_w, Bh, Bl, DD, FF_);
        dim3 gF1(FF_ / 128, ROWS / 128, 1);
        mma_gemm<<<gF1, 256, GSMEM>>>(Ah, Al, DD, 0, 0, Bh, Bl, DD, 0, 0,
                                      ffn, FF_, 0, 0, fc_in_b, nullptr, 0, 0, 0, DD, 1, 1, 0);
    }

    // 10. out0 = ffn @ fc_out + b + h2
    decomp4_kernel<<<(int)((long long)ROWS * FF_ / 4 / 256), 256>>>(ffn, Ah, Al);
    {
        dim3 gW2(FF_ / 32, DD / 32);
        wtrans_kernel<<<gW2, 256>>>(fc_out_w, Bh, Bl, FF_, DD);
        dim3 gF2(DD / 128, ROWS / 128, 1);
        mma_gemm<<<gF2, 256, GSMEM>>>(Ah, Al, FF_, 0, 0, Bh, Bl, FF_, 0, 0,
                                      out0, DD, 0, 0, fc_out_b, h, DD, 0, 0, FF_, 1, 0, 0);
    }
}

// round 5
// speedup vs baseline: 5.9849x; 1.1457x over previous
#include <cuda_runtime.h>
#include <cuda_bf16.h>
#include <math.h>
#include <stdint.h>

// Problem dims (fixed)
#define BB 2
#define SS_ 2048
#define DD 2048
#define HH 16
#define DH_ 128
#define FF_ 8192
#define ROWS 4096            // B*S

// ---------------- scratch ----------------
__device__ float g_h   [(size_t)ROWS * DD];   // h2 (LN2 out, fp32)
__device__ float g_q   [(size_t)ROWS * DD];
__device__ float g_k   [(size_t)ROWS * DD];
__device__ float g_v   [(size_t)ROWS * DD];
__device__ float g_res [(size_t)ROWS * DD];

#define AMAX ((size_t)BB * HH * SS_ * SS_)
#define BMAX ((size_t)DD * FF_)
#define CMAX ((size_t)ROWS * FF_)
__device__ __nv_bfloat16 g_Ah[AMAX];
__device__ __nv_bfloat16 g_Al[AMAX];
__device__ __nv_bfloat16 g_Bh[BMAX];
__device__ __nv_bfloat16 g_Bl[BMAX];
__device__ __nv_bfloat16 g_Ch[CMAX];
__device__ __nv_bfloat16 g_Cl[CMAX];

__device__ __forceinline__ uint32_t smem_u32(const void* p) {
    uint32_t a;
    asm("{ .reg .u64 t; cvta.to.shared.u64 t, %1; cvt.u32.u64 %0, t; }" : "=r"(a) : "l"(p));
    return a;
}

#define LDMX4(r0, r1, r2, r3, addr) \
    asm volatile("ldmatrix.sync.aligned.m8n8.x4.shared.b16 {%0,%1,%2,%3}, [%4];" \
                 : "=r"(r0), "=r"(r1), "=r"(r2), "=r"(r3) : "r"(addr))

#define MMA16816(c, a, b0, b1) \
    asm volatile("mma.sync.aligned.m16n8k16.row.col.f32.bf16.bf16.f32 " \
                 "{%0,%1,%2,%3}, {%4,%5,%6,%7}, {%8,%9}, {%0,%1,%2,%3};" \
                 : "+f"((c)[0]), "+f"((c)[1]), "+f"((c)[2]), "+f"((c)[3]) \
                 : "r"((a)[0]), "r"((a)[1]), "r"((a)[2]), "r"((a)[3]), \
                   "r"(b0), "r"(b1))

#define CP16(dst, src) \
    asm volatile("cp.async.cg.shared.global [%0], [%1], 16;" :: "r"(dst), "l"(src))
#define CP_COMMIT() asm volatile("cp.async.commit_group;" ::: "memory")
#define CP_WAIT1()  asm volatile("cp.async.wait_group 1;" ::: "memory")

__device__ __forceinline__ void decomp2_store(__nv_bfloat16* hp, __nv_bfloat16* lp,
                                              long long off, float x, float y) {
    __nv_bfloat16 hx = __float2bfloat16(x);
    __nv_bfloat16 hy = __float2bfloat16(y);
    *(__nv_bfloat162*)(hp + off) = __nv_bfloat162(hx, hy);
    *(__nv_bfloat162*)(lp + off) = __nv_bfloat162(__float2bfloat16(x - __bfloat162float(hx)),
                                                  __float2bfloat16(y - __bfloat162float(hy)));
}

// ===================== LayerNorm fused with bf16 decompose =====================
__global__ void ln_fused_kernel(const float* __restrict__ x,
                                const float* __restrict__ g,
                                const float* __restrict__ b,
                                float* __restrict__ out,          // may be null
                                __nv_bfloat16* __restrict__ oh,
                                __nv_bfloat16* __restrict__ ol) {
    __shared__ float xs[DD];
    __shared__ float red[256];
    const int row = blockIdx.x;
    const int tid = threadIdx.x;
    const float* xr = x + (long long)row * DD;

    float s = 0.f;
    for (int i = tid; i < DD; i += 256) { float t = xr[i]; xs[i] = t; s += t; }
    red[tid] = s; __syncthreads();
    for (int o = 128; o > 0; o >>= 1) { if (tid < o) red[tid] += red[tid + o]; __syncthreads(); }
    const float mean = red[0] * (1.f / DD);
    __syncthreads();

    float v = 0.f;
    for (int i = tid; i < DD; i += 256) { float d = xs[i] - mean; v += d * d; }
    red[tid] = v; __syncthreads();
    for (int o = 128; o > 0; o >>= 1) { if (tid < o) red[tid] += red[tid + o]; __syncthreads(); }
    const float rstd = rsqrtf(red[0] * (1.f / DD) + 1e-5f);

    const long long base = (long long)row * DD;
    for (int i = tid * 2; i < DD; i += 512) {
        float a0 = (xs[i] - mean) * rstd * g[i] + b[i];
        float a1 = (xs[i + 1] - mean) * rstd * g[i + 1] + b[i + 1];
        if (out) *(float2*)(out + base + i) = make_float2(a0, a1);
        decomp2_store(oh, ol, base + i, a0, a1);
    }
}

// ===================== RoPE fused with decompose (q->Ah/Al, k->Bh/Bl) ==========
__global__ void rope_decomp_kernel(const float* __restrict__ q,
                                   const float* __restrict__ k,
                                   const int* __restrict__ pos,
                                   __nv_bfloat16* __restrict__ qh, __nv_bfloat16* __restrict__ ql,
                                   __nv_bfloat16* __restrict__ kh, __nv_bfloat16* __restrict__ kl) {
    long long idx = (long long)blockIdx.x * blockDim.x + threadIdx.x;
    const long long total = (long long)ROWS * HH * 64;
    if (idx >= total) return;
    const int i = (int)(idx & 63);
    long long t = idx >> 6;
    const int h = (int)(t % HH); t /= HH;
    const int s = (int)(t % SS_);
    const int b = (int)(t / SS_);

    const int p = pos[b * SS_ + s];
    const float inv = exp10f(-(float)i * (1.f / 16.f));
    const float ang = (float)p * inv;
    const float sn = sinf(ang), cs = cosf(ang);

    const long long base = ((((long long)b * SS_ + s) * HH + h) * DH_) + 2 * i;
    {
        float x0 = q[base], x1 = q[base + 1];
        decomp2_store(qh, ql, base, x0 * cs - x1 * sn, x1 * cs + x0 * sn);
    }
    {
        float x0 = k[base], x1 = k[base + 1];
        decomp2_store(kh, kl, base, x0 * cs - x1 * sn, x1 * cs + x0 * sn);
    }
}

// ===================== softmax in place + decompose =====================
__global__ void softmax_kernel(float* __restrict__ w,
                               __nv_bfloat16* __restrict__ oh,
                               __nv_bfloat16* __restrict__ ol) {
    __shared__ float sc[SS_];
    __shared__ float red[256];
    const int qi = blockIdx.x, h = blockIdx.y, b = blockIdx.z;
    const int tid = threadIdx.x;
    const long long rbase = ((long long)(b * HH + h) * SS_ + qi) * SS_;
    float* wrow = w + rbase;
    const int n = qi + 1;

    float lmax = -1e30f;
    for (int j = tid; j < n; j += 256) { float t = wrow[j]; sc[j] = t; lmax = fmaxf(lmax, t); }
    red[tid] = lmax; __syncthreads();
    for (int o = 128; o > 0; o >>= 1) { if (tid < o) red[tid] = fmaxf(red[tid], red[tid + o]); __syncthreads(); }
    const float gmax = red[0];
    __syncthreads();

    float lsum = 0.f;
    for (int j = tid; j < n; j += 256) { float e = expf(sc[j] - gmax); sc[j] = e; lsum += e; }
    red[tid] = lsum; __syncthreads();
    for (int o = 128; o > 0; o >>= 1) { if (tid < o) red[tid] += red[tid + o]; __syncthreads(); }
    const float inv = 1.f / red[0];
    __syncthreads();

    for (int j = tid * 2; j < SS_; j += 512) {
        float x = (j < n) ? sc[j] * inv : 0.f;
        float y = (j + 1 < n) ? sc[j + 1] * inv : 0.f;
        *(float2*)(wrow + j) = make_float2(x, y);
        decomp2_store(oh, ol, rbase + j, x, y);
    }
}

// ===================== transpose+decompose weight [K,N] -> [N,K] =====================
__global__ void wtrans_kernel(const float* __restrict__ w,
                              __nv_bfloat16* __restrict__ bh,
                              __nv_bfloat16* __restrict__ bl,
                              int Kdim, int Ndim) {
    __shared__ float t[32][33];
    const int k0 = blockIdx.x * 32, n0 = blockIdx.y * 32;
    const int tx = threadIdx.x & 31, ty = threadIdx.x >> 5;
#pragma unroll
    for (int i = 0; i < 32; i += 8)
        t[ty + i][tx] = w[(long long)(k0 + ty + i) * Ndim + n0 + tx];
    __syncthreads();
#pragma unroll
    for (int i = 0; i < 32; i += 8) {
        float v = t[tx][ty + i];
        long long o = (long long)(n0 + ty + i) * Kdim + k0 + tx;
        __nv_bfloat16 h = __float2bfloat16(v);
        bh[o] = h;
        bl[o] = __float2bfloat16(v - __bfloat162float(h));
    }
}

// ===================== transpose+decompose V [B,S,H,DH] -> [B,H,DH,S] ==========
__global__ void vtrans_kernel(const float* __restrict__ v,
                              __nv_bfloat16* __restrict__ bh,
                              __nv_bfloat16* __restrict__ bl) {
    __shared__ float t[32][33];
    const int bh_i = blockIdx.z;
    const int b = bh_i >> 4, h = bh_i & 15;
    const int s0 = blockIdx.x * 32, d0 = blockIdx.y * 32;
    const int tx = threadIdx.x & 31, ty = threadIdx.x >> 5;
#pragma unroll
    for (int i = 0; i < 32; i += 8)
        t[ty + i][tx] = v[(((long long)b * SS_ + s0 + ty + i) * HH + h) * DH_ + d0 + tx];
    __syncthreads();
#pragma unroll
    for (int i = 0; i < 32; i += 8) {
        float val = t[tx][ty + i];
        long long o = ((long long)bh_i * DH_ + d0 + ty + i) * SS_ + s0 + tx;
        __nv_bfloat16 hh2 = __float2bfloat16(val);
        bh[o] = hh2;
        bl[o] = __float2bfloat16(val - __bfloat162float(hh2));
    }
}

// ===================== pipelined mma.sync bf16x3 GEMM, BK=64 =====================
// out = act( A @ B^T + bias ) [+ res]; A[M,K], B[N,K] hi/lo bf16 K-major
// C (fp32, optional) and/or Oh/Ol (bf16 hi/lo, optional) share ldc/strides.
// causal: 0 none, 1 skip blocks col0>row0+127, 2 limit K to row0+128
#define SA 72
#define STAGES 3
#define TILEB (128 * SA * 2)
#define STAGEB (4 * TILEB)
#define GSMEM (STAGES * STAGEB)

__global__ __launch_bounds__(256) void mma_gemm(
        const __nv_bfloat16* __restrict__ Ah, const __nv_bfloat16* __restrict__ Al,
        int lda, long long sAb, long long sAhS,
        const __nv_bfloat16* __restrict__ Bh, const __nv_bfloat16* __restrict__ Bl,
        int ldb, long long sBb, long long sBhS,
        float* __restrict__ C,
        __nv_bfloat16* __restrict__ Oh, __nv_bfloat16* __restrict__ Ol,
        int ldc, long long sCb, long long sCh,
        const float* __restrict__ bias,
        const float* __restrict__ res, int ldr, long long sRb, long long sRh,
        int K, int Hb, int act, int causal) {
    extern __shared__ char dsm[];

    const int row0 = blockIdx.y * 128;
    const int col0 = blockIdx.x * 128;
    if (causal == 1 && col0 > row0 + 127) return;

    const int tid = threadIdx.x;
    const int warp = tid >> 5, lane = tid & 31;
    const int wm = warp >> 2, wn = warp & 3;

    const int bz = blockIdx.z;
    const int b = bz / Hb, hh = bz % Hb;
    Ah += b * sAb + hh * sAhS;
    Al += b * sAb + hh * sAhS;
    Bh += b * sBb + hh * sBhS;
    Bl += b * sBb + hh * sBhS;
    const long long cOff = b * sCb + hh * sCh;
    if (C)  C += cOff;
    if (Oh) { Oh += cOff; Ol += cOff; }
    if (res) res += b * sRb + hh * sRh;

    const uint32_t u0 = smem_u32(dsm);

    float acc[4][4][4] = {};

    const int lr = tid >> 3, lc = (tid & 7) * 8;
    const int a_r = lane & 15, a_c = (lane >> 4) * 8;
    const int b_r = ((lane >> 4) << 3) + (lane & 7), b_c = ((lane >> 3) & 1) * 8;

    int nch = K / 64;
    if (causal == 2) { int lim = (row0 + 128 + 63) / 64; if (lim < nch) nch = lim; }

    auto load_chunk = [&](int ch, int st) {
        const int kb = ch * 64;
        const uint32_t base = u0 + st * STAGEB;
#pragma unroll
        for (int p = 0; p < 4; p++) {
            const int r = lr + p * 32;
            const long long ga = (long long)(row0 + r) * lda + kb + lc;
            const long long gb = (long long)(col0 + r) * ldb + kb + lc;
            const uint32_t so = (uint32_t)(r * SA + lc) * 2;
            CP16(base + so,             Ah + ga);
            CP16(base + TILEB + so,     Al + ga);
            CP16(base + 2 * TILEB + so, Bh + gb);
            CP16(base + 3 * TILEB + so, Bl + gb);
        }
    };

    for (int ch = 0; ch < STAGES - 1; ch++) {
        if (ch < nch) load_chunk(ch, ch);
        CP_COMMIT();
    }

    for (int ch = 0; ch < nch; ch++) {
        CP_WAIT1();
        __syncthreads();
        const int nx = ch + STAGES - 1;
        if (nx < nch) load_chunk(nx, nx % STAGES);
        CP_COMMIT();

        const uint32_t base = u0 + (ch % STAGES) * STAGEB;
        const uint32_t uAh = base, uAl = base + TILEB;
        const uint32_t uBh = base + 2 * TILEB, uBl = base + 3 * TILEB;

#pragma unroll
        for (int ks = 0; ks < 4; ks++) {
            const int kc = ks * 16;
            uint32_t af[4][4], fbh[2][4], fbl[2][4];
#pragma unroll
            for (int nb = 0; nb < 2; nb++) {
                const uint32_t off = (uint32_t)((wn * 32 + nb * 16 + b_r) * SA + kc + b_c) * 2;
                LDMX4(fbh[nb][0], fbh[nb][1], fbh[nb][2], fbh[nb][3], uBh + off);
                LDMX4(fbl[nb][0], fbl[nb][1], fbl[nb][2], fbl[nb][3], uBl + off);
            }
#pragma unroll
            for (int mi = 0; mi < 4; mi++) {
                const uint32_t off = (uint32_t)((wm * 64 + mi * 16 + a_r) * SA + kc + a_c) * 2;
                LDMX4(af[mi][0], af[mi][1], af[mi][2], af[mi][3], uAh + off);
            }
#pragma unroll
            for (int mi = 0; mi < 4; mi++)
#pragma unroll
                for (int ni = 0; ni < 4; ni++) {
                    MMA16816(acc[mi][ni], af[mi], fbh[ni >> 1][(ni & 1) * 2], fbh[ni >> 1][(ni & 1) * 2 + 1]);
                    MMA16816(acc[mi][ni], af[mi], fbl[ni >> 1][(ni & 1) * 2], fbl[ni >> 1][(ni & 1) * 2 + 1]);
                }
#pragma unroll
            for (int mi = 0; mi < 4; mi++) {
                const uint32_t off = (uint32_t)((wm * 64 + mi * 16 + a_r) * SA + kc + a_c) * 2;
                LDMX4(af[mi][0], af[mi][1], af[mi][2], af[mi][3], uAl + off);
            }
#pragma unroll
            for (int mi = 0; mi < 4; mi++)
#pragma unroll
                for (int ni = 0; ni < 4; ni++)
                    MMA16816(acc[mi][ni], af[mi], fbh[ni >> 1][(ni & 1) * 2], fbh[ni >> 1][(ni & 1) * 2 + 1]);
        }
        __syncthreads();
    }

    // epilogue
#pragma unroll
    for (int mi = 0; mi < 4; mi++) {
#pragma unroll
        for (int ni = 0; ni < 4; ni++) {
#pragma unroll
            for (int half = 0; half < 2; half++) {
                const long long r = row0 + wm * 64 + mi * 16 + (lane >> 2) + half * 8;
                const int cc = col0 + wn * 32 + ni * 8 + (lane & 3) * 2;
                float x = acc[mi][ni][half * 2];
                float y = acc[mi][ni][half * 2 + 1];
                if (bias) { x += bias[cc]; y += bias[cc + 1]; }
                if (act == 1) {
                    x = 0.5f * x * (1.f + erff(x * 0.70710678118654752f));
                    y = 0.5f * y * (1.f + erff(y * 0.70710678118654752f));
                }
                if (res) {
                    x += res[r * ldr + cc];
                    y += res[r * ldr + cc + 1];
                }
                if (C) *(float2*)(C + r * ldc + cc) = make_float2(x, y);
                if (Oh) decomp2_store(Oh, Ol, r * ldc + cc, x, y);
            }
        }
    }
}

// ===================== host launch =====================
extern "C" void kernel_launch(void* const* d_in, const int* in_sizes, int n_in,
                              void* d_out, int out_size) {
    const float* hidden  = (const float*)d_in[0];
    const int*   pos     = (const int*)  d_in[1];
    const float* wq      = (const float*)d_in[2];
    const float* wk      = (const float*)d_in[3];
    const float* wv      = (const float*)d_in[4];
    const float* wo      = (const float*)d_in[5];
    const float* ln1_g   = (const float*)d_in[6];
    const float* ln1_b   = (const float*)d_in[7];
    const float* ln2_g   = (const float*)d_in[8];
    const float* ln2_b   = (const float*)d_in[9];
    const float* fc_in_w = (const float*)d_in[10];
    const float* fc_in_b = (const float*)d_in[11];
    const float* fc_out_w= (const float*)d_in[12];
    const float* fc_out_b= (const float*)d_in[13];

    float* out0 = (float*)d_out;                               // [B,S,D]
    float* out1 = out0 + (long long)BB * SS_ * DD;             // [B,H,S,S]

    float *h, *q, *k, *v, *res;
    __nv_bfloat16 *Ah, *Al, *Bh, *Bl, *Ch, *Cl;
    cudaGetSymbolAddress((void**)&h,   g_h);
    cudaGetSymbolAddress((void**)&q,   g_q);
    cudaGetSymbolAddress((void**)&k,   g_k);
    cudaGetSymbolAddress((void**)&v,   g_v);
    cudaGetSymbolAddress((void**)&res, g_res);
    cudaGetSymbolAddress((void**)&Ah,  g_Ah);
    cudaGetSymbolAddress((void**)&Al,  g_Al);
    cudaGetSymbolAddress((void**)&Bh,  g_Bh);
    cudaGetSymbolAddress((void**)&Bl,  g_Bl);
    cudaGetSymbolAddress((void**)&Ch,  g_Ch);
    cudaGetSymbolAddress((void**)&Cl,  g_Cl);

    cudaFuncSetAttribute(mma_gemm, cudaFuncAttributeMaxDynamicSharedMemorySize, GSMEM);

    // 1. LN1 -> bf16 hi/lo only
    ln_fused_kernel<<<ROWS, 256>>>(hidden, ln1_g, ln1_b, nullptr, Ah, Al);

    // 2. QKV (fp32 outputs; q,k consumed by rope, v by vtrans)
    dim3 gQ(DD / 128, ROWS / 128, 1);
    dim3 gW(DD / 32, DD / 32);
    wtrans_kernel<<<gW, 256>>>(wq, Bh, Bl, DD, DD);
    mma_gemm<<<gQ, 256, GSMEM>>>(Ah, Al, DD, 0, 0, Bh, Bl, DD, 0, 0,
                                 q, nullptr, nullptr, DD, 0, 0,
                                 nullptr, nullptr, 0, 0, 0, DD, 1, 0, 0);
    wtrans_kernel<<<gW, 256>>>(wk, Bh, Bl, DD, DD);
    mma_gemm<<<gQ, 256, GSMEM>>>(Ah, Al, DD, 0, 0, Bh, Bl, DD, 0, 0,
                                 k, nullptr, nullptr, DD, 0, 0,
                                 nullptr, nullptr, 0, 0, 0, DD, 1, 0, 0);
    wtrans_kernel<<<gW, 256>>>(wv, Bh, Bl, DD, DD);
    mma_gemm<<<gQ, 256, GSMEM>>>(Ah, Al, DD, 0, 0, Bh, Bl, DD, 0, 0,
                                 v, nullptr, nullptr, DD, 0, 0,
                                 nullptr, nullptr, 0, 0, 0, DD, 1, 0, 0);

    // 3. RoPE + decompose: q->Ah/Al, k->Bh/Bl
    {
        long long total = (long long)ROWS * HH * 64;
        rope_decomp_kernel<<<(int)((total + 255) / 256), 256>>>(q, k, pos, Ah, Al, Bh, Bl);
    }

    // 4. scores = q @ k^T (causal blocks) -> out1 fp32
    {
        dim3 gS(SS_ / 128, SS_ / 128, BB * HH);
        mma_gemm<<<gS, 256, GSMEM>>>(
            Ah, Al, DD, (long long)SS_ * DD, DH_,
            Bh, Bl, DD, (long long)SS_ * DD, DH_,
            out1, nullptr, nullptr, SS_, (long long)HH * SS_ * SS_, (long long)SS_ * SS_,
            nullptr, nullptr, 0, 0, 0, DH_, HH, 0, 1);
    }

    // 5. softmax in place + decompose -> Ah/Al
    {
        dim3 gA(SS_, HH, BB);
        softmax_kernel<<<gA, 256>>>(out1, Ah, Al);
    }

    // 6. v^T decompose -> Bh/Bl; ctx = weights @ v (bf16 hi/lo out -> Ch/Cl)
    {
        dim3 gVT(SS_ / 32, DH_ / 32, BB * HH);
        vtrans_kernel<<<gVT, 256>>>(v, Bh, Bl);
        dim3 gV(DH_ / 128, SS_ / 128, BB * HH);
        mma_gemm<<<gV, 256, GSMEM>>>(
            Ah, Al, SS_, (long long)HH * SS_ * SS_, (long long)SS_ * SS_,
            Bh, Bl, SS_, (long long)HH * DH_ * SS_, (long long)DH_ * SS_,
            nullptr, Ch, Cl, DD, (long long)SS_ * DD, DH_,
            nullptr, nullptr, 0, 0, 0, SS_, HH, 0, 2);
    }

    // 7. res = ctx @ wo + hidden (fp32)
    wtrans_kernel<<<gW, 256>>>(wo, Bh, Bl, DD, DD);
    mma_gemm<<<gQ, 256, GSMEM>>>(Ch, Cl, DD, 0, 0, Bh, Bl, DD, 0, 0,
                                 res, nullptr, nullptr, DD, 0, 0,
                                 nullptr, hidden, DD, 0, 0, DD, 1, 0, 0);

    // 8. LN2 -> h fp32 + Ah/Al
    ln_fused_kernel<<<ROWS, 256>>>(res, ln2_g, ln2_b, h, Ah, Al);

    // 9. ffn = gelu(h2 @ fc_in + b) -> bf16 hi/lo Ch/Cl (no fp32)
    {
        dim3 gW1(DD / 32, FF_ / 32);
        wtrans_kernel<<<gW1, 256>>>(fc_in_w, Bh, Bl, DD, FF_);
        dim3 gF1(FF_ / 128, ROWS / 128, 1);
        mma_gemm<<<gF1, 256, GSMEM>>>(Ah, Al, DD, 0, 0, Bh, Bl, DD, 0, 0,
                                      nullptr, Ch, Cl, FF_, 0, 0,
                                      fc_in_b, nullptr, 0, 0, 0, DD, 1, 1, 0);
    }

    // 10. out0 = ffn @ fc_out + b + h2
    {
        dim3 gW2(FF_ / 32, DD / 32);
        wtrans_kernel<<<gW2, 256>>>(fc_out_w, Bh, Bl, FF_, DD);
        dim3 gF2(DD / 128, ROWS / 128, 1);
        mma_gemm<<<gF2, 256, GSMEM>>>(Ch, Cl, FF_, 0, 0, Bh, Bl, FF_, 0, 0,
                                      out0, nullptr, nullptr, DD, 0, 0,
                                      fc_out_b, h, DD, 0, 0, FF_, 1, 0, 0);
    }
}

// round 6
// speedup vs baseline: 6.3529x; 1.0615x over previous
#include <cuda_runtime.h>
#include <cuda_bf16.h>
#include <math.h>
#include <stdint.h>

// Problem dims (fixed)
#define BB 2
#define SS_ 2048
#define DD 2048
#define HH 16
#define DH_ 128
#define FF_ 8192
#define ROWS 4096            // B*S

// ---------------- scratch ----------------
__device__ float g_h   [(size_t)ROWS * DD];   // h2 (LN2 out, fp32)
__device__ float g_v   [(size_t)ROWS * DD];
__device__ float g_res [(size_t)ROWS * DD];

#define AMAX ((size_t)BB * HH * SS_ * SS_)
#define BMAX ((size_t)DD * FF_)
#define CMAX ((size_t)ROWS * FF_)
__device__ __nv_bfloat16 g_Ah[AMAX];
__device__ __nv_bfloat16 g_Al[AMAX];
__device__ __nv_bfloat16 g_Bh[BMAX];
__device__ __nv_bfloat16 g_Bl[BMAX];
__device__ __nv_bfloat16 g_Ch[CMAX];
__device__ __nv_bfloat16 g_Cl[CMAX];
__device__ __nv_bfloat16 g_Kh[(size_t)ROWS * DD];
__device__ __nv_bfloat16 g_Kl[(size_t)ROWS * DD];

__device__ __forceinline__ uint32_t smem_u32(const void* p) {
    uint32_t a;
    asm("{ .reg .u64 t; cvta.to.shared.u64 t, %1; cvt.u32.u64 %0, t; }" : "=r"(a) : "l"(p));
    return a;
}

#define LDMX4(r0, r1, r2, r3, addr) \
    asm volatile("ldmatrix.sync.aligned.m8n8.x4.shared.b16 {%0,%1,%2,%3}, [%4];" \
                 : "=r"(r0), "=r"(r1), "=r"(r2), "=r"(r3) : "r"(addr))

#define MMA16816(c, a, b0, b1) \
    asm volatile("mma.sync.aligned.m16n8k16.row.col.f32.bf16.bf16.f32 " \
                 "{%0,%1,%2,%3}, {%4,%5,%6,%7}, {%8,%9}, {%0,%1,%2,%3};" \
                 : "+f"((c)[0]), "+f"((c)[1]), "+f"((c)[2]), "+f"((c)[3]) \
                 : "r"((a)[0]), "r"((a)[1]), "r"((a)[2]), "r"((a)[3]), \
                   "r"(b0), "r"(b1))

#define CP16(dst, src) \
    asm volatile("cp.async.cg.shared.global [%0], [%1], 16;" :: "r"(dst), "l"(src))
#define CP_COMMIT() asm volatile("cp.async.commit_group;" ::: "memory")
#define CP_WAIT0()  asm volatile("cp.async.wait_group 0;" ::: "memory")

__device__ __forceinline__ void decomp2_store(__nv_bfloat16* hp, __nv_bfloat16* lp,
                                              long long off, float x, float y) {
    __nv_bfloat16 hx = __float2bfloat16(x);
    __nv_bfloat16 hy = __float2bfloat16(y);
    *(__nv_bfloat162*)(hp + off) = __nv_bfloat162(hx, hy);
    *(__nv_bfloat162*)(lp + off) = __nv_bfloat162(__float2bfloat16(x - __bfloat162float(hx)),
                                                  __float2bfloat16(y - __bfloat162float(hy)));
}

// ===================== LayerNorm fused with bf16 decompose =====================
__global__ void ln_fused_kernel(const float* __restrict__ x,
                                const float* __restrict__ g,
                                const float* __restrict__ b,
                                float* __restrict__ out,          // may be null
                                __nv_bfloat16* __restrict__ oh,
                                __nv_bfloat16* __restrict__ ol) {
    __shared__ float xs[DD];
    __shared__ float red[256];
    const int row = blockIdx.x;
    const int tid = threadIdx.x;
    const float* xr = x + (long long)row * DD;

    float s = 0.f;
    for (int i = tid; i < DD; i += 256) { float t = xr[i]; xs[i] = t; s += t; }
    red[tid] = s; __syncthreads();
    for (int o = 128; o > 0; o >>= 1) { if (tid < o) red[tid] += red[tid + o]; __syncthreads(); }
    const float mean = red[0] * (1.f / DD);
    __syncthreads();

    float v = 0.f;
    for (int i = tid; i < DD; i += 256) { float d = xs[i] - mean; v += d * d; }
    red[tid] = v; __syncthreads();
    for (int o = 128; o > 0; o >>= 1) { if (tid < o) red[tid] += red[tid + o]; __syncthreads(); }
    const float rstd = rsqrtf(red[0] * (1.f / DD) + 1e-5f);

    const long long base = (long long)row * DD;
    for (int i = tid * 2; i < DD; i += 512) {
        float a0 = (xs[i] - mean) * rstd * g[i] + b[i];
        float a1 = (xs[i + 1] - mean) * rstd * g[i + 1] + b[i + 1];
        if (out) *(float2*)(out + base + i) = make_float2(a0, a1);
        decomp2_store(oh, ol, base + i, a0, a1);
    }
}

// ===================== softmax in place + decompose =====================
__global__ void softmax_kernel(float* __restrict__ w,
                               __nv_bfloat16* __restrict__ oh,
                               __nv_bfloat16* __restrict__ ol) {
    __shared__ float sc[SS_];
    __shared__ float red[256];
    const int qi = blockIdx.x, h = blockIdx.y, b = blockIdx.z;
    const int tid = threadIdx.x;
    const long long rbase = ((long long)(b * HH + h) * SS_ + qi) * SS_;
    float* wrow = w + rbase;
    const int n = qi + 1;

    float lmax = -1e30f;
    for (int j = tid; j < n; j += 256) { float t = wrow[j]; sc[j] = t; lmax = fmaxf(lmax, t); }
    red[tid] = lmax; __syncthreads();
    for (int o = 128; o > 0; o >>= 1) { if (tid < o) red[tid] = fmaxf(red[tid], red[tid + o]); __syncthreads(); }
    const float gmax = red[0];
    __syncthreads();

    float lsum = 0.f;
    for (int j = tid; j < n; j += 256) { float e = expf(sc[j] - gmax); sc[j] = e; lsum += e; }
    red[tid] = lsum; __syncthreads();
    for (int o = 128; o > 0; o >>= 1) { if (tid < o) red[tid] += red[tid + o]; __syncthreads(); }
    const float inv = 1.f / red[0];
    __syncthreads();

    for (int j = tid * 2; j < SS_; j += 512) {
        float x = (j < n) ? sc[j] * inv : 0.f;
        float y = (j + 1 < n) ? sc[j + 1] * inv : 0.f;
        *(float2*)(wrow + j) = make_float2(x, y);
        decomp2_store(oh, ol, rbase + j, x, y);
    }
}

// ===================== transpose+decompose weight [K,N] -> [N,K] =====================
__global__ void wtrans_kernel(const float* __restrict__ w,
                              __nv_bfloat16* __restrict__ bh,
                              __nv_bfloat16* __restrict__ bl,
                              int Kdim, int Ndim) {
    __shared__ float t[32][33];
    const int k0 = blockIdx.x * 32, n0 = blockIdx.y * 32;
    const int tx = threadIdx.x & 31, ty = threadIdx.x >> 5;
#pragma unroll
    for (int i = 0; i < 32; i += 8)
        t[ty + i][tx] = w[(long long)(k0 + ty + i) * Ndim + n0 + tx];
    __syncthreads();
#pragma unroll
    for (int i = 0; i < 32; i += 8) {
        float v = t[tx][ty + i];
        long long o = (long long)(n0 + ty + i) * Kdim + k0 + tx;
        __nv_bfloat16 h = __float2bfloat16(v);
        bh[o] = h;
        bl[o] = __float2bfloat16(v - __bfloat162float(h));
    }
}

// ===================== transpose+decompose V [B,S,H,DH] -> [B,H,DH,S] ==========
__global__ void vtrans_kernel(const float* __restrict__ v,
                              __nv_bfloat16* __restrict__ bh,
                              __nv_bfloat16* __restrict__ bl) {
    __shared__ float t[32][33];
    const int bh_i = blockIdx.z;
    const int b = bh_i >> 4, h = bh_i & 15;
    const int s0 = blockIdx.x * 32, d0 = blockIdx.y * 32;
    const int tx = threadIdx.x & 31, ty = threadIdx.x >> 5;
#pragma unroll
    for (int i = 0; i < 32; i += 8)
        t[ty + i][tx] = v[(((long long)b * SS_ + s0 + ty + i) * HH + h) * DH_ + d0 + tx];
    __syncthreads();
#pragma unroll
    for (int i = 0; i < 32; i += 8) {
        float val = t[tx][ty + i];
        long long o = ((long long)bh_i * DH_ + d0 + ty + i) * SS_ + s0 + tx;
        __nv_bfloat16 hh2 = __float2bfloat16(val);
        bh[o] = hh2;
        bl[o] = __float2bfloat16(val - __bfloat162float(hh2));
    }
}

// ===================== pipelined mma.sync bf16x3 GEMM, BK=32, 2-stage, 2 CTA/SM ==
// out = act( A @ B^T + bias ) [+ res]; A[M,K], B[N,K] hi/lo bf16 K-major
// act: 0 none, 1 gelu, 2 rope (uses pos, writes hi/lo)
// causal: 0 none, 1 skip blocks col0>row0+127, 2 limit K to row0+128
#define SA 40
#define TILEB (128 * SA * 2)
#define STAGEB (4 * TILEB)
#define GSMEM (2 * STAGEB)

__global__ __launch_bounds__(256, 2) void mma_gemm(
        const __nv_bfloat16* __restrict__ Ah, const __nv_bfloat16* __restrict__ Al,
        int lda, long long sAb, long long sAhS,
        const __nv_bfloat16* __restrict__ Bh, const __nv_bfloat16* __restrict__ Bl,
        int ldb, long long sBb, long long sBhS,
        float* __restrict__ C,
        __nv_bfloat16* __restrict__ Oh, __nv_bfloat16* __restrict__ Ol,
        int ldc, long long sCb, long long sCh,
        const float* __restrict__ bias,
        const float* __restrict__ res, int ldr, long long sRb, long long sRh,
        const int* __restrict__ pos,
        int K, int Hb, int act, int causal) {
    extern __shared__ char dsm[];

    const int row0 = blockIdx.y * 128;
    const int col0 = blockIdx.x * 128;
    if (causal == 1 && col0 > row0 + 127) return;

    const int tid = threadIdx.x;
    const int warp = tid >> 5, lane = tid & 31;
    const int wm = warp >> 2, wn = warp & 3;

    const int bz = blockIdx.z;
    const int b = bz / Hb, hh = bz % Hb;
    Ah += b * sAb + hh * sAhS;
    Al += b * sAb + hh * sAhS;
    Bh += b * sBb + hh * sBhS;
    Bl += b * sBb + hh * sBhS;
    const long long cOff = b * sCb + hh * sCh;
    if (C)  C += cOff;
    if (Oh) { Oh += cOff; Ol += cOff; }
    if (res) res += b * sRb + hh * sRh;

    const uint32_t u0 = smem_u32(dsm);

    float acc[4][4][4] = {};

    const int lr0 = tid >> 2, lc = (tid & 3) * 8;
    const int a_r = lane & 15, a_c = (lane >> 4) * 8;
    const int b_r = ((lane >> 4) << 3) + (lane & 7), b_c = ((lane >> 3) & 1) * 8;

    int nch = K / 32;
    if (causal == 2) { int lim = (row0 + 128) / 32; if (lim < nch) nch = lim; }

    auto load_chunk = [&](int ch, int st) {
        const int kb = ch * 32;
        const uint32_t base = u0 + st * STAGEB;
#pragma unroll
        for (int p = 0; p < 2; p++) {
            const int r = lr0 + p * 64;
            const long long ga = (long long)(row0 + r) * lda + kb + lc;
            const long long gb = (long long)(col0 + r) * ldb + kb + lc;
            const uint32_t so = (uint32_t)(r * SA + lc) * 2;
            CP16(base + so,             Ah + ga);
            CP16(base + TILEB + so,     Al + ga);
            CP16(base + 2 * TILEB + so, Bh + gb);
            CP16(base + 3 * TILEB + so, Bl + gb);
        }
    };

    load_chunk(0, 0);
    CP_COMMIT();

    for (int ch = 0; ch < nch; ch++) {
        CP_WAIT0();
        __syncthreads();
        if (ch + 1 < nch) { load_chunk(ch + 1, (ch + 1) & 1); CP_COMMIT(); }

        const uint32_t base = u0 + (ch & 1) * STAGEB;
        const uint32_t uAh = base, uAl = base + TILEB;
        const uint32_t uBh = base + 2 * TILEB, uBl = base + 3 * TILEB;

#pragma unroll
        for (int ks = 0; ks < 2; ks++) {
            const int kc = ks * 16;
            uint32_t af[4][4], fbh[2][4], fbl[2][4];
#pragma unroll
            for (int nb = 0; nb < 2; nb++) {
                const uint32_t off = (uint32_t)((wn * 32 + nb * 16 + b_r) * SA + kc + b_c) * 2;
                LDMX4(fbh[nb][0], fbh[nb][1], fbh[nb][2], fbh[nb][3], uBh + off);
                LDMX4(fbl[nb][0], fbl[nb][1], fbl[nb][2], fbl[nb][3], uBl + off);
            }
#pragma unroll
            for (int mi = 0; mi < 4; mi++) {
                const uint32_t off = (uint32_t)((wm * 64 + mi * 16 + a_r) * SA + kc + a_c) * 2;
                LDMX4(af[mi][0], af[mi][1], af[mi][2], af[mi][3], uAh + off);
            }
#pragma unroll
            for (int mi = 0; mi < 4; mi++)
#pragma unroll
                for (int ni = 0; ni < 4; ni++) {
                    MMA16816(acc[mi][ni], af[mi], fbh[ni >> 1][(ni & 1) * 2], fbh[ni >> 1][(ni & 1) * 2 + 1]);
                    MMA16816(acc[mi][ni], af[mi], fbl[ni >> 1][(ni & 1) * 2], fbl[ni >> 1][(ni & 1) * 2 + 1]);
                }
#pragma unroll
            for (int mi = 0; mi < 4; mi++) {
                const uint32_t off = (uint32_t)((wm * 64 + mi * 16 + a_r) * SA + kc + a_c) * 2;
                LDMX4(af[mi][0], af[mi][1], af[mi][2], af[mi][3], uAl + off);
            }
#pragma unroll
            for (int mi = 0; mi < 4; mi++)
#pragma unroll
                for (int ni = 0; ni < 4; ni++)
                    MMA16816(acc[mi][ni], af[mi], fbh[ni >> 1][(ni & 1) * 2], fbh[ni >> 1][(ni & 1) * 2 + 1]);
        }
        __syncthreads();
    }

    // epilogue
#pragma unroll
    for (int mi = 0; mi < 4; mi++) {
#pragma unroll
        for (int ni = 0; ni < 4; ni++) {
#pragma unroll
            for (int half = 0; half < 2; half++) {
                const long long r = row0 + wm * 64 + mi * 16 + (lane >> 2) + half * 8;
                const int cc = col0 + wn * 32 + ni * 8 + (lane & 3) * 2;
                float x = acc[mi][ni][half * 2];
                float y = acc[mi][ni][half * 2 + 1];
                if (bias) { x += bias[cc]; y += bias[cc + 1]; }
                if (act == 1) {
                    x = 0.5f * x * (1.f + erff(x * 0.70710678118654752f));
                    y = 0.5f * y * (1.f + erff(y * 0.70710678118654752f));
                } else if (act == 2) {
                    const int i = (cc & (DH_ - 1)) >> 1;
                    const float ang = (float)pos[r] * exp10f(-(float)i * (1.f / 16.f));
                    const float sn = sinf(ang), cs = cosf(ang);
                    const float nx = x * cs - y * sn;
                    y = y * cs + x * sn;
                    x = nx;
                }
                if (res) {
                    x += res[r * ldr + cc];
                    y += res[r * ldr + cc + 1];
                }
                if (C) *(float2*)(C + r * ldc + cc) = make_float2(x, y);
                if (Oh) decomp2_store(Oh, Ol, r * ldc + cc, x, y);
            }
        }
    }
}

// ===================== host launch =====================
extern "C" void kernel_launch(void* const* d_in, const int* in_sizes, int n_in,
                              void* d_out, int out_size) {
    const float* hidden  = (const float*)d_in[0];
    const int*   pos     = (const int*)  d_in[1];
    const float* wq      = (const float*)d_in[2];
    const float* wk      = (const float*)d_in[3];
    const float* wv      = (const float*)d_in[4];
    const float* wo      = (const float*)d_in[5];
    const float* ln1_g   = (const float*)d_in[6];
    const float* ln1_b   = (const float*)d_in[7];
    const float* ln2_g   = (const float*)d_in[8];
    const float* ln2_b   = (const float*)d_in[9];
    const float* fc_in_w = (const float*)d_in[10];
    const float* fc_in_b = (const float*)d_in[11];
    const float* fc_out_w= (const float*)d_in[12];
    const float* fc_out_b= (const float*)d_in[13];

    float* out0 = (float*)d_out;                               // [B,S,D]
    float* out1 = out0 + (long long)BB * SS_ * DD;             // [B,H,S,S]

    float *h, *v, *res;
    __nv_bfloat16 *Ah, *Al, *Bh, *Bl, *Ch, *Cl, *Kh, *Kl;
    cudaGetSymbolAddress((void**)&h,   g_h);
    cudaGetSymbolAddress((void**)&v,   g_v);
    cudaGetSymbolAddress((void**)&res, g_res);
    cudaGetSymbolAddress((void**)&Ah,  g_Ah);
    cudaGetSymbolAddress((void**)&Al,  g_Al);
    cudaGetSymbolAddress((void**)&Bh,  g_Bh);
    cudaGetSymbolAddress((void**)&Bl,  g_Bl);
    cudaGetSymbolAddress((void**)&Ch,  g_Ch);
    cudaGetSymbolAddress((void**)&Cl,  g_Cl);
    cudaGetSymbolAddress((void**)&Kh,  g_Kh);
    cudaGetSymbolAddress((void**)&Kl,  g_Kl);

    cudaFuncSetAttribute(mma_gemm, cudaFuncAttributeMaxDynamicSharedMemorySize, GSMEM);

    // 1. LN1 -> bf16 hi/lo only
    ln_fused_kernel<<<ROWS, 256>>>(hidden, ln1_g, ln1_b, nullptr, Ah, Al);

    // 2. QKV. q,k fuse RoPE in epilogue and emit hi/lo directly; v stays fp32.
    dim3 gQ(DD / 128, ROWS / 128, 1);
    dim3 gW(DD / 32, DD / 32);
    wtrans_kernel<<<gW, 256>>>(wq, Bh, Bl, DD, DD);
    mma_gemm<<<gQ, 256, GSMEM>>>(Ah, Al, DD, 0, 0, Bh, Bl, DD, 0, 0,
                                 nullptr, Ch, Cl, DD, 0, 0,
                                 nullptr, nullptr, 0, 0, 0, pos, DD, 1, 2, 0);
    wtrans_kernel<<<gW, 256>>>(wk, Bh, Bl, DD, DD);
    mma_gemm<<<gQ, 256, GSMEM>>>(Ah, Al, DD, 0, 0, Bh, Bl, DD, 0, 0,
                                 nullptr, Kh, Kl, DD, 0, 0,
                                 nullptr, nullptr, 0, 0, 0, pos, DD, 1, 2, 0);
    wtrans_kernel<<<gW, 256>>>(wv, Bh, Bl, DD, DD);
    mma_gemm<<<gQ, 256, GSMEM>>>(Ah, Al, DD, 0, 0, Bh, Bl, DD, 0, 0,
                                 v, nullptr, nullptr, DD, 0, 0,
                                 nullptr, nullptr, 0, 0, 0, nullptr, DD, 1, 0, 0);

    // 3. scores = q @ k^T (causal blocks) -> out1 fp32
    {
        dim3 gS(SS_ / 128, SS_ / 128, BB * HH);
        mma_gemm<<<gS, 256, GSMEM>>>(
            Ch, Cl, DD, (long long)SS_ * DD, DH_,
            Kh, Kl, DD, (long long)SS_ * DD, DH_,
            out1, nullptr, nullptr, SS_, (long long)HH * SS_ * SS_, (long long)SS_ * SS_,
            nullptr, nullptr, 0, 0, 0, nullptr, DH_, HH, 0, 1);
    }

    // 4. softmax in place + decompose -> Ah/Al
    {
        dim3 gA(SS_, HH, BB);
        softmax_kernel<<<gA, 256>>>(out1, Ah, Al);
    }

    // 5. v^T decompose -> Bh/Bl; ctx = weights @ v (bf16 hi/lo -> Ch/Cl)
    {
        dim3 gVT(SS_ / 32, DH_ / 32, BB * HH);
        vtrans_kernel<<<gVT, 256>>>(v, Bh, Bl);
        dim3 gV(DH_ / 128, SS_ / 128, BB * HH);
        mma_gemm<<<gV, 256, GSMEM>>>(
            Ah, Al, SS_, (long long)HH * SS_ * SS_, (long long)SS_ * SS_,
            Bh, Bl, SS_, (long long)HH * DH_ * SS_, (long long)DH_ * SS_,
            nullptr, Ch, Cl, DD, (long long)SS_ * DD, DH_,
            nullptr, nullptr, 0, 0, 0, nullptr, SS_, HH, 0, 2);
    }

    // 6. res = ctx @ wo + hidden (fp32)
    wtrans_kernel<<<gW, 256>>>(wo, Bh, Bl, DD, DD);
    mma_gemm<<<gQ, 256, GSMEM>>>(Ch, Cl, DD, 0, 0, Bh, Bl, DD, 0, 0,
                                 res, nullptr, nullptr, DD, 0, 0,
                                 nullptr, hidden, DD, 0, 0, nullptr, DD, 1, 0, 0);

    // 7. LN2 -> h fp32 + Ah/Al
    ln_fused_kernel<<<ROWS, 256>>>(res, ln2_g, ln2_b, h, Ah, Al);

    // 8. ffn = gelu(h2 @ fc_in + b) -> bf16 hi/lo Ch/Cl (no fp32)
    {
        dim3 gW1(DD / 32, FF_ / 32);
        wtrans_kernel<<<gW1, 256>>>(fc_in_w, Bh, Bl, DD, FF_);
        dim3 gF1(FF_ / 128, ROWS / 128, 1);
        mma_gemm<<<gF1, 256, GSMEM>>>(Ah, Al, DD, 0, 0, Bh, Bl, DD, 0, 0,
                                      nullptr, Ch, Cl, FF_, 0, 0,
                                      fc_in_b, nullptr, 0, 0, 0, nullptr, DD, 1, 1, 0);
    }

    // 9. out0 = ffn @ fc_out + b + h2
    {
        dim3 gW2(FF_ / 32, DD / 32);
        wtrans_kernel<<<gW2, 256>>>(fc_out_w, Bh, Bl, FF_, DD);
        dim3 gF2(DD / 128, ROWS / 128, 1);
        mma_gemm<<<gF2, 256, GSMEM>>>(Ch, Cl, FF_, 0, 0, Bh, Bl, FF_, 0, 0,
                                      out0, nullptr, nullptr, DD, 0, 0,
                                      fc_out_b, h, DD, 0, 0, nullptr, FF_, 1, 0, 0);
    }
}